// round 9
// baseline (speedup 1.0000x reference)
#include <cuda_runtime.h>
#include <cuda_bf16.h>
#include <cstdint>
#include <math.h>

#define DM 512
#define DI 2048
#define NH 8
#define DKH 64
#define BSZ 32
#define MAXROWS (32*160)
#define MAXKV   (32*640)

// ---- fp32 scratch ----
__device__ float g_Q  [MAXROWS*DM];
__device__ float g_K  [MAXKV*DM];
__device__ float g_V  [MAXKV*DM];
__device__ float g_t0 [MAXROWS*DM];
__device__ float g_x  [MAXROWS*DM];

// ---- bf16 hi/lo scratch (16B-aligned for bulk-copy sources) ----
__device__ __align__(16) __nv_bfloat16 g_predH[MAXKV*DM],   g_predL[MAXKV*DM];
__device__ __align__(16) __nv_bfloat16 g_entH [MAXROWS*DM], g_entL [MAXROWS*DM];
__device__ __align__(16) __nv_bfloat16 g_ctxH [MAXROWS*DM], g_ctxL [MAXROWS*DM];
__device__ __align__(16) __nv_bfloat16 g_xH   [MAXROWS*DM], g_xL   [MAXROWS*DM];
__device__ __align__(16) __nv_bfloat16 g_hH   [MAXROWS*DI], g_hL   [MAXROWS*DI];
__device__ __align__(16) __nv_bfloat16 g_wqH[DM*DM], g_wqL[DM*DM];
__device__ __align__(16) __nv_bfloat16 g_wkH[DM*DM], g_wkL[DM*DM];
__device__ __align__(16) __nv_bfloat16 g_wvH[DM*DM], g_wvL[DM*DM];
__device__ __align__(16) __nv_bfloat16 g_wfH[DM*DM], g_wfL[DM*DM];
__device__ __align__(16) __nv_bfloat16 g_w1H[DI*DM], g_w1L[DI*DM];
__device__ __align__(16) __nv_bfloat16 g_w2H[DM*DI], g_w2L[DM*DI];

__device__ __forceinline__ unsigned pack_bf2(float a, float b) {
    __nv_bfloat162 t = __floats2bfloat162_rn(a, b);
    return *(unsigned*)&t;
}

// ============================================================
// fp32 -> bf16 hi/lo conversion
// ============================================================
__global__ void cvt_hl(const float* __restrict__ in,
                       __nv_bfloat16* __restrict__ hi,
                       __nv_bfloat16* __restrict__ lo, int n4)
{
    int i = blockIdx.x * blockDim.x + threadIdx.x;
    if (i >= n4) return;
    float4 v = ((const float4*)in)[i];
    float h0 = __bfloat162float(__float2bfloat16(v.x));
    float h1 = __bfloat162float(__float2bfloat16(v.y));
    float h2 = __bfloat162float(__float2bfloat16(v.z));
    float h3 = __bfloat162float(__float2bfloat16(v.w));
    uint2 uh, ul;
    uh.x = pack_bf2(v.x, v.y);
    uh.y = pack_bf2(v.z, v.w);
    ul.x = pack_bf2(v.x - h0, v.y - h1);
    ul.y = pack_bf2(v.z - h2, v.w - h3);
    *(uint2*)(hi + 4 * (size_t)i) = uh;
    *(uint2*)(lo + 4 * (size_t)i) = ul;
}

// ============================================================
// Bulk-copy pipelined GEMM: C[M,N] = A[M,K] @ W[N,K]^T + bias.
// A,W bf16 hi/lo; 3 mma passes, fp32 accum.
// 128x128 tile, BK=64, 3-stage cp.async.bulk + mbarrier ring.
// Rows padded to 144B (conflict-free ldmatrix). 256 thr, 1 CTA/SM.
// ============================================================
#define QBM 128
#define QBN 128
#define QBK 64
#define ROWB 144
#define TILE_B (128*ROWB)          // 18432
#define STAGE_B (4*TILE_B)         // 73728
#define GEMM_SMEM (3*STAGE_B)      // 221184
#define STAGE_TX 65536             // 4 tiles * 128 rows * 128B

__device__ __forceinline__ unsigned smem_u32(const void* p) {
    return (unsigned)__cvta_generic_to_shared(p);
}
__device__ __forceinline__ void bulk128(unsigned dst, const void* src, unsigned mbar) {
    asm volatile(
        "cp.async.bulk.shared::cta.global.mbarrier::complete_tx::bytes [%0], [%1], 128, [%2];"
        :: "r"(dst), "l"(src), "r"(mbar) : "memory");
}
__device__ __forceinline__ void mbar_init(unsigned addr, unsigned cnt) {
    asm volatile("mbarrier.init.shared.b64 [%0], %1;" :: "r"(addr), "r"(cnt) : "memory");
}
__device__ __forceinline__ void mbar_arrive(unsigned addr) {
    asm volatile("mbarrier.arrive.shared.b64 _, [%0];" :: "r"(addr) : "memory");
}
__device__ __forceinline__ void mbar_expect_tx(unsigned addr, unsigned bytes) {
    asm volatile("mbarrier.arrive.expect_tx.shared.b64 _, [%0], %1;"
        :: "r"(addr), "r"(bytes) : "memory");
}
__device__ __forceinline__ void mbar_wait(unsigned addr, unsigned parity) {
    asm volatile(
        "{\n\t.reg .pred P;\n\t"
        "W_%=: mbarrier.try_wait.parity.acquire.cta.shared::cta.b64 P, [%0], %1, 0x989680;\n\t"
        "@P bra D_%=;\n\t"
        "bra W_%=;\n\t"
        "D_%=:\n\t}"
        :: "r"(addr), "r"(parity) : "memory");
}
__device__ __forceinline__ void ldsm_x4(unsigned* r, const void* p) {
    unsigned a = smem_u32(p);
    asm volatile("ldmatrix.sync.aligned.m8n8.x4.shared.b16 {%0,%1,%2,%3}, [%4];"
        : "=r"(r[0]), "=r"(r[1]), "=r"(r[2]), "=r"(r[3]) : "r"(a));
}
__device__ __forceinline__ void ldsm_x2(unsigned* r, const void* p) {
    unsigned a = smem_u32(p);
    asm volatile("ldmatrix.sync.aligned.m8n8.x2.shared.b16 {%0,%1}, [%2];"
        : "=r"(r[0]), "=r"(r[1]) : "r"(a));
}
__device__ __forceinline__ void mma16816(float* c, const unsigned* a, const unsigned* b) {
    asm volatile("mma.sync.aligned.m16n8k16.row.col.f32.bf16.bf16.f32 "
        "{%0,%1,%2,%3}, {%4,%5,%6,%7}, {%8,%9}, {%0,%1,%2,%3};"
        : "+f"(c[0]), "+f"(c[1]), "+f"(c[2]), "+f"(c[3])
        : "r"(a[0]), "r"(a[1]), "r"(a[2]), "r"(a[3]), "r"(b[0]), "r"(b[1]));
}

__global__ __launch_bounds__(256, 1)
void gemm_blk(const __nv_bfloat16* __restrict__ Ah, const __nv_bfloat16* __restrict__ Al,
              const int* __restrict__ rmap,
              const __nv_bfloat16* __restrict__ Wh, const __nv_bfloat16* __restrict__ Wl,
              const float* __restrict__ bias,
              float* __restrict__ Cf,
              __nv_bfloat16* __restrict__ Ch, __nv_bfloat16* __restrict__ Cl,
              int M, int N, int K, int relu)
{
    extern __shared__ char sm[];
    __shared__ __align__(8) unsigned long long mbar_st[6];  // full0..2, empty0..2
    __shared__ int irows[QBM];

    const int tid  = threadIdx.x;
    const int lane = tid & 31;
    const int wid  = tid >> 5;
    const int wm   = wid >> 2;
    const int wn   = wid & 3;
    const int bm = blockIdx.y * QBM;
    const int bn = blockIdx.x * QBN;

    if (tid < QBM) {
        int ar = bm + tid;
        irows[tid] = (ar < M) ? (rmap ? rmap[ar] : ar) : -1;
    }
    if (tid == 0) {
        #pragma unroll
        for (int s = 0; s < 3; ++s) {
            mbar_init(smem_u32(&mbar_st[s]), 1);        // full: 1 arrival (expect_tx)
            mbar_init(smem_u32(&mbar_st[3 + s]), 256);  // empty: all threads
        }
    }
    __syncthreads();

    unsigned mb_full[3], mb_empty[3];
    #pragma unroll
    for (int s = 0; s < 3; ++s) {
        mb_full[s]  = smem_u32(&mbar_st[s]);
        mb_empty[s] = smem_u32(&mbar_st[3 + s]);
    }
    const unsigned smb = smem_u32(sm);
    const __nv_bfloat16* srcs[4] = {Ah, Al, Wh, Wl};
    const int nIter = K / QBK;

    float acc[4][4][4];
    #pragma unroll
    for (int mi = 0; mi < 4; ++mi) {
        #pragma unroll
        for (int ni = 0; ni < 4; ++ni) {
            #pragma unroll
            for (int j = 0; j < 4; ++j) acc[mi][ni][j] = 0.f;
        }
    }

    // issue one stage: 512 row-copies spread over 256 threads (2 each)
    auto issue = [&](int s, int k0) {
        if (tid == 0) mbar_expect_tx(mb_full[s], STAGE_TX);
        #pragma unroll
        for (int i = 0; i < 2; ++i) {
            int idx = tid + i * 256;
            int buf = idx >> 7;
            int r   = idx & 127;
            int grow;
            if (buf < 2) {
                grow = irows[r];
                if (grow < 0) grow = irows[0];   // OOB rows: fetch valid data, discard later
            } else {
                grow = bn + r;                   // N multiple of 128 -> always valid
            }
            const char* src = (const char*)srcs[buf] + ((size_t)grow * K + k0) * 2;
            unsigned dst = smb + s * STAGE_B + buf * TILE_B + r * ROWB;
            bulk128(dst, src, mb_full[s]);
        }
    };

    // prologue: fill stages 0..2 (nIter >= 8 always)
    issue(0, 0);
    issue(1, QBK);
    issue(2, 2 * QBK);

    int s = 0, par = 0;
    for (int c = 0; c < nIter; ++c) {
        mbar_wait(mb_full[s], par);

        const char* st  = sm + s * STAGE_B;
        const char* tAh = st;
        const char* tAl = st + TILE_B;
        const char* tWh = st + 2 * TILE_B;
        const char* tWl = st + 3 * TILE_B;

        #pragma unroll
        for (int ks = 0; ks < 4; ++ks) {
            const int kb = ks * 32;   // 16 elems * 2B
            unsigned ah[4][4], al[4][4], bh[4][2], bl[4][2];
            const int lr = lane & 15;
            const int lkb = (lane >> 4) * 16;   // 8 elems * 2B
            #pragma unroll
            for (int mi = 0; mi < 4; ++mi) {
                int ro = (wm * 64 + mi * 16 + lr) * ROWB + kb + lkb;
                ldsm_x4(ah[mi], tAh + ro);
                ldsm_x4(al[mi], tAl + ro);
            }
            const int l8 = lane & 7;
            const int lkb2 = ((lane >> 3) & 1) * 16;
            #pragma unroll
            for (int ni = 0; ni < 4; ++ni) {
                int ro = (wn * 32 + ni * 8 + l8) * ROWB + kb + lkb2;
                ldsm_x2(bh[ni], tWh + ro);
                ldsm_x2(bl[ni], tWl + ro);
            }
            #pragma unroll
            for (int mi = 0; mi < 4; ++mi) {
                #pragma unroll
                for (int ni = 0; ni < 4; ++ni) {
                    mma16816(acc[mi][ni], ah[mi], bh[ni]);
                    mma16816(acc[mi][ni], ah[mi], bl[ni]);
                    mma16816(acc[mi][ni], al[mi], bh[ni]);
                }
            }
        }

        mbar_arrive(mb_empty[s]);
        if (c + 3 < nIter) {
            mbar_wait(mb_empty[s], par);   // all 256 done with this stage
            issue(s, (c + 3) * QBK);
        }
        ++s;
        if (s == 3) { s = 0; par ^= 1; }
    }

    // ---- epilogue ----
    #pragma unroll
    for (int mi = 0; mi < 4; ++mi) {
        int r0 = bm + wm * 64 + mi * 16 + (lane >> 2);
        #pragma unroll
        for (int ni = 0; ni < 4; ++ni) {
            int c = bn + wn * 32 + ni * 8 + (lane & 3) * 2;
            float b0 = bias[c];
            float b1 = bias[c + 1];
            float v0 = acc[mi][ni][0] + b0;
            float v1 = acc[mi][ni][1] + b1;
            float v2 = acc[mi][ni][2] + b0;
            float v3 = acc[mi][ni][3] + b1;
            if (relu) {
                v0 = fmaxf(v0, 0.f); v1 = fmaxf(v1, 0.f);
                v2 = fmaxf(v2, 0.f); v3 = fmaxf(v3, 0.f);
            }
            if (r0 < M) {
                size_t o = (size_t)r0 * N + c;
                if (Cf) *(float2*)(Cf + o) = make_float2(v0, v1);
                if (Ch) {
                    float h0 = __bfloat162float(__float2bfloat16(v0));
                    float h1 = __bfloat162float(__float2bfloat16(v1));
                    *(unsigned*)(Ch + o) = pack_bf2(v0, v1);
                    *(unsigned*)(Cl + o) = pack_bf2(v0 - h0, v1 - h1);
                }
            }
            if (r0 + 8 < M) {
                size_t o = (size_t)(r0 + 8) * N + c;
                if (Cf) *(float2*)(Cf + o) = make_float2(v2, v3);
                if (Ch) {
                    float h2 = __bfloat162float(__float2bfloat16(v2));
                    float h3 = __bfloat162float(__float2bfloat16(v3));
                    *(unsigned*)(Ch + o) = pack_bf2(v2, v3);
                    *(unsigned*)(Cl + o) = pack_bf2(v2 - h2, v3 - h3);
                }
            }
        }
    }
}

// ============================================================
// LayerNorm with residual; optional bf16 hi/lo secondary output.
// ============================================================
__global__ void ln_res(const float* __restrict__ A, const float* __restrict__ R,
                       const int* __restrict__ rmap,
                       const float* __restrict__ g, const float* __restrict__ beta,
                       float* __restrict__ out,
                       __nv_bfloat16* __restrict__ outH, __nv_bfloat16* __restrict__ outL)
{
    int row = blockIdx.x;
    int tid = threadIdx.x;   // 128
    __shared__ float red [128];
    __shared__ float red2[128];
    int rrow = rmap ? rmap[row] : row;
    float4 x = ((const float4*)(A + (size_t)row*DM))[tid];
    float4 r = ((const float4*)(R + (size_t)rrow*DM))[tid];
    x.x += r.x; x.y += r.y; x.z += r.z; x.w += r.w;
    red [tid] = x.x + x.y + x.z + x.w;
    red2[tid] = x.x*x.x + x.y*x.y + x.z*x.z + x.w*x.w;
    __syncthreads();
    #pragma unroll
    for (int o = 64; o > 0; o >>= 1) {
        if (tid < o) { red[tid] += red[tid+o]; red2[tid] += red2[tid+o]; }
        __syncthreads();
    }
    float mean = red[0] * (1.f/512.f);
    float var  = red2[0] * (1.f/512.f) - mean*mean;
    float inv  = rsqrtf(var + 1e-5f);
    float4 gg = ((const float4*)g)[tid];
    float4 bb = ((const float4*)beta)[tid];
    float4 o4;
    o4.x = (x.x - mean)*inv*gg.x + bb.x;
    o4.y = (x.y - mean)*inv*gg.y + bb.y;
    o4.z = (x.z - mean)*inv*gg.z + bb.z;
    o4.w = (x.w - mean)*inv*gg.w + bb.w;
    ((float4*)(out + (size_t)row*DM))[tid] = o4;
    if (outH) {
        size_t o = (size_t)row * DM + tid * 4;
        float h0 = __bfloat162float(__float2bfloat16(o4.x));
        float h1 = __bfloat162float(__float2bfloat16(o4.y));
        float h2 = __bfloat162float(__float2bfloat16(o4.z));
        float h3 = __bfloat162float(__float2bfloat16(o4.w));
        uint2 uh, ul;
        uh.x = pack_bf2(o4.x, o4.y);
        uh.y = pack_bf2(o4.z, o4.w);
        ul.x = pack_bf2(o4.x - h0, o4.y - h1);
        ul.y = pack_bf2(o4.z - h2, o4.w - h3);
        *(uint2*)(outH + o) = uh;
        *(uint2*)(outL + o) = ul;
    }
}

// ============================================================
// Flash-style attention; writes ctx directly as bf16 hi/lo.
// ============================================================
__global__ __launch_bounds__(128, 8)
void attn_flash(const float* __restrict__ Q, const float* __restrict__ Kb,
                const float* __restrict__ Vb, const int* __restrict__ mask,
                __nv_bfloat16* __restrict__ ctxH, __nv_bfloat16* __restrict__ ctxL,
                int Lq, int Lv)
{
    const int qt = blockIdx.x;
    const int h  = blockIdx.y;
    const int b  = blockIdx.z;
    const int t  = threadIdx.x;
    const int tq = t >> 3;
    const int kc = t & 7;
    const int q  = qt * 16 + tq;
    const bool qvalid = q < Lq;
    const int d0 = kc * 8;

    __shared__ float sQ[16][68];
    __shared__ float sK[32][68];
    __shared__ float sV[32][68];
    __shared__ float sP[16][36];

    #pragma unroll
    for (int i = 0; i < 2; ++i) {
        int idx = t + i * 128;
        int r  = idx >> 4;
        int c4 = idx & 15;
        int qq = qt * 16 + r;
        float4 v = make_float4(0.f, 0.f, 0.f, 0.f);
        if (qq < Lq) {
            v = *(const float4*)(Q + ((size_t)(b * Lq + qq)) * DM + h * DKH + c4 * 4);
        }
        *(float4*)&sQ[r][c4 * 4] = v;
    }

    float acc[8] = {0.f, 0.f, 0.f, 0.f, 0.f, 0.f, 0.f, 0.f};
    float m_run = -INFINITY;
    float l_run = 0.f;
    const int* mrow = mask + ((size_t)(b * Lq + (qvalid ? q : 0))) * Lv;

    for (int kv0 = 0; kv0 < Lv; kv0 += 32) {
        __syncthreads();
        #pragma unroll
        for (int i = 0; i < 4; ++i) {
            int idx = t + i * 128;
            int r  = idx >> 4;
            int c4 = idx & 15;
            int kv = kv0 + r;
            float4 kvv = make_float4(0.f, 0.f, 0.f, 0.f);
            float4 vvv = make_float4(0.f, 0.f, 0.f, 0.f);
            if (kv < Lv) {
                size_t base = ((size_t)(b * Lv + kv)) * DM + h * DKH + c4 * 4;
                kvv = *(const float4*)(Kb + base);
                vvv = *(const float4*)(Vb + base);
            }
            *(float4*)&sK[r][c4 * 4] = kvv;
            *(float4*)&sV[r][c4 * 4] = vvv;
        }
        __syncthreads();

        float s[4];
        #pragma unroll
        for (int c = 0; c < 4; ++c) {
            int k  = kc * 4 + c;
            int kv = kv0 + k;
            bool msk = true;
            if (qvalid && kv < Lv) {
                msk = (mrow[kv] != 0);
            }
            float a = 0.f;
            #pragma unroll
            for (int d4 = 0; d4 < 16; ++d4) {
                float4 qv = *(const float4*)&sQ[tq][d4 * 4];
                float4 kk = *(const float4*)&sK[k][d4 * 4];
                a += qv.x*kk.x + qv.y*kk.y + qv.z*kk.z + qv.w*kk.w;
            }
            s[c] = msk ? -INFINITY : a * 0.125f;
        }
        float tm = fmaxf(fmaxf(s[0], s[1]), fmaxf(s[2], s[3]));
        tm = fmaxf(tm, __shfl_xor_sync(0xffffffffu, tm, 1));
        tm = fmaxf(tm, __shfl_xor_sync(0xffffffffu, tm, 2));
        tm = fmaxf(tm, __shfl_xor_sync(0xffffffffu, tm, 4));
        float newm  = fmaxf(m_run, tm);
        float scale = __expf(fminf(m_run - newm, 0.f));
        float ts = 0.f;
        #pragma unroll
        for (int c = 0; c < 4; ++c) {
            float p = (s[c] == -INFINITY) ? 0.f : __expf(s[c] - newm);
            sP[tq][kc * 4 + c] = p;
            ts += p;
        }
        ts += __shfl_xor_sync(0xffffffffu, ts, 1);
        ts += __shfl_xor_sync(0xffffffffu, ts, 2);
        ts += __shfl_xor_sync(0xffffffffu, ts, 4);
        l_run = l_run * scale + ts;
        m_run = newm;
        #pragma unroll
        for (int j = 0; j < 8; ++j) acc[j] *= scale;
        __syncwarp();

        #pragma unroll 8
        for (int k = 0; k < 32; ++k) {
            float p = sP[tq][k];
            float4 v0 = *(const float4*)&sV[k][d0];
            float4 v1 = *(const float4*)&sV[k][d0 + 4];
            acc[0] += p * v0.x; acc[1] += p * v0.y; acc[2] += p * v0.z; acc[3] += p * v0.w;
            acc[4] += p * v1.x; acc[5] += p * v1.y; acc[6] += p * v1.z; acc[7] += p * v1.w;
        }
    }

    if (qvalid) {
        float inv = 1.f / l_run;
        float o[8];
        #pragma unroll
        for (int j = 0; j < 8; ++j) o[j] = acc[j] * inv;
        size_t off = ((size_t)(b * Lq + q)) * DM + h * DKH + d0;
        uint4 uh, ul;
        uh.x = pack_bf2(o[0], o[1]); uh.y = pack_bf2(o[2], o[3]);
        uh.z = pack_bf2(o[4], o[5]); uh.w = pack_bf2(o[6], o[7]);
        float hh[8];
        #pragma unroll
        for (int j = 0; j < 8; ++j) hh[j] = __bfloat162float(__float2bfloat16(o[j]));
        ul.x = pack_bf2(o[0]-hh[0], o[1]-hh[1]); ul.y = pack_bf2(o[2]-hh[2], o[3]-hh[3]);
        ul.z = pack_bf2(o[4]-hh[4], o[5]-hh[5]); ul.w = pack_bf2(o[6]-hh[6], o[7]-hh[7]);
        *(uint4*)(ctxH + off) = uh;
        *(uint4*)(ctxL + off) = ul;
    }
}

// ============================================================
// launcher
// ============================================================
extern "C" void kernel_launch(void* const* d_in, const int* in_sizes, int n_in,
                              void* d_out, int out_size)
{
    const float* ent   = (const float*)d_in[0];
    const float* pred  = (const float*)d_in[1];
    const float* w_qs  = (const float*)d_in[2];
    const float* b_qs  = (const float*)d_in[3];
    const float* w_ks  = (const float*)d_in[4];
    const float* b_ks  = (const float*)d_in[5];
    const float* w_vs  = (const float*)d_in[6];
    const float* b_vs  = (const float*)d_in[7];
    const float* w_fc  = (const float*)d_in[8];
    const float* b_fc  = (const float*)d_in[9];
    const float* ln1_g = (const float*)d_in[10];
    const float* ln1_b = (const float*)d_in[11];
    const float* w1    = (const float*)d_in[12];
    const float* b1    = (const float*)d_in[13];
    const float* w2    = (const float*)d_in[14];
    const float* b2    = (const float*)d_in[15];
    const float* ln2_g = (const float*)d_in[16];
    const float* ln2_b = (const float*)d_in[17];
    const int*   amask = (const int*)d_in[18];
    const int*   gidx  = (const int*)d_in[20];

    int Lq  = in_sizes[0] / (BSZ * DM);
    int Lv  = in_sizes[1] / (BSZ * DM);
    int nv  = in_sizes[20];
    int MKV = BSZ * Lv;
    int MQ  = BSZ * Lq;

    float *pQ, *pK, *pV, *pT0, *pX;
    cudaGetSymbolAddress((void**)&pQ,  g_Q);
    cudaGetSymbolAddress((void**)&pK,  g_K);
    cudaGetSymbolAddress((void**)&pV,  g_V);
    cudaGetSymbolAddress((void**)&pT0, g_t0);
    cudaGetSymbolAddress((void**)&pX,  g_x);

    __nv_bfloat16 *predH,*predL,*entH,*entL,*ctxH,*ctxL,*xH,*xL,*hH,*hL;
    __nv_bfloat16 *wqH,*wqL,*wkH,*wkL,*wvH,*wvL,*wfH,*wfL,*w1H,*w1L,*w2H,*w2L;
    cudaGetSymbolAddress((void**)&predH, g_predH); cudaGetSymbolAddress((void**)&predL, g_predL);
    cudaGetSymbolAddress((void**)&entH,  g_entH);  cudaGetSymbolAddress((void**)&entL,  g_entL);
    cudaGetSymbolAddress((void**)&ctxH,  g_ctxH);  cudaGetSymbolAddress((void**)&ctxL,  g_ctxL);
    cudaGetSymbolAddress((void**)&xH,    g_xH);    cudaGetSymbolAddress((void**)&xL,    g_xL);
    cudaGetSymbolAddress((void**)&hH,    g_hH);    cudaGetSymbolAddress((void**)&hL,    g_hL);
    cudaGetSymbolAddress((void**)&wqH,   g_wqH);   cudaGetSymbolAddress((void**)&wqL,   g_wqL);
    cudaGetSymbolAddress((void**)&wkH,   g_wkH);   cudaGetSymbolAddress((void**)&wkL,   g_wkL);
    cudaGetSymbolAddress((void**)&wvH,   g_wvH);   cudaGetSymbolAddress((void**)&wvL,   g_wvL);
    cudaGetSymbolAddress((void**)&wfH,   g_wfH);   cudaGetSymbolAddress((void**)&wfL,   g_wfL);
    cudaGetSymbolAddress((void**)&w1H,   g_w1H);   cudaGetSymbolAddress((void**)&w1L,   g_w1L);
    cudaGetSymbolAddress((void**)&w2H,   g_w2H);   cudaGetSymbolAddress((void**)&w2L,   g_w2L);

    cudaFuncSetAttribute(gemm_blk, cudaFuncAttributeMaxDynamicSharedMemorySize, GEMM_SMEM);

    int n4;
    // K path first: GEMM lands at launch index 2 for the profiler
    n4 = MKV * DM / 4;  cvt_hl<<<(n4 + 255) / 256, 256>>>(pred, predH, predL, n4);
    n4 = DM * DM / 4;   cvt_hl<<<(n4 + 255) / 256, 256>>>(w_ks, wkH, wkL, n4);
    {
        dim3 grd(DM / QBN, (MKV + QBM - 1) / QBM);
        gemm_blk<<<grd, 256, GEMM_SMEM>>>(predH, predL, nullptr, wkH, wkL, b_ks,
                                          pK, nullptr, nullptr, MKV, DM, DM, 0);
    }
    n4 = DM * DM / 4;   cvt_hl<<<(n4 + 255) / 256, 256>>>(w_vs, wvH, wvL, n4);
    {
        dim3 grd(DM / QBN, (MKV + QBM - 1) / QBM);
        gemm_blk<<<grd, 256, GEMM_SMEM>>>(predH, predL, nullptr, wvH, wvL, b_vs,
                                          pV, nullptr, nullptr, MKV, DM, DM, 0);
    }
    n4 = MQ * DM / 4;   cvt_hl<<<(n4 + 255) / 256, 256>>>(ent, entH, entL, n4);
    n4 = DM * DM / 4;   cvt_hl<<<(n4 + 255) / 256, 256>>>(w_qs, wqH, wqL, n4);
    {
        dim3 grd(DM / QBN, (MQ + QBM - 1) / QBM);
        gemm_blk<<<grd, 256, GEMM_SMEM>>>(entH, entL, nullptr, wqH, wqL, b_qs,
                                          pQ, nullptr, nullptr, MQ, DM, DM, 0);
    }
    // attention -> ctx (bf16 HL, padded)
    {
        dim3 grd((Lq + 15) / 16, NH, BSZ);
        attn_flash<<<grd, 128>>>(pQ, pK, pV, amask, ctxH, ctxL, Lq, Lv);
    }
    // fc projection (gathers valid rows) + LN1
    n4 = DM * DM / 4;   cvt_hl<<<(n4 + 255) / 256, 256>>>(w_fc, wfH, wfL, n4);
    {
        dim3 grd(DM / QBN, (nv + QBM - 1) / QBM);
        gemm_blk<<<grd, 256, GEMM_SMEM>>>(ctxH, ctxL, gidx, wfH, wfL, b_fc,
                                          pT0, nullptr, nullptr, nv, DM, DM, 0);
        ln_res<<<nv, 128>>>(pT0, ent, gidx, ln1_g, ln1_b, pX, xH, xL);
    }
    // FFN
    n4 = DI * DM / 4;   cvt_hl<<<(n4 + 255) / 256, 256>>>(w1, w1H, w1L, n4);
    {
        dim3 grd(DI / QBN, (nv + QBM - 1) / QBM);
        gemm_blk<<<grd, 256, GEMM_SMEM>>>(xH, xL, nullptr, w1H, w1L, b1,
                                          nullptr, hH, hL, nv, DI, DM, 1);
    }
    n4 = DM * DI / 4;   cvt_hl<<<(n4 + 255) / 256, 256>>>(w2, w2H, w2L, n4);
    {
        dim3 grd(DM / QBN, (nv + QBM - 1) / QBM);
        gemm_blk<<<grd, 256, GEMM_SMEM>>>(hH, hL, nullptr, w2H, w2L, b2,
                                          pT0, nullptr, nullptr, nv, DM, DI, 0);
        ln_res<<<nv, 128>>>(pT0, pX, nullptr, ln2_g, ln2_b, (float*)d_out, nullptr, nullptr);
    }
}

// round 10
// speedup vs baseline: 1.3531x; 1.3531x over previous
#include <cuda_runtime.h>
#include <cuda_fp16.h>
#include <cstdint>
#include <math.h>

#define DM 512
#define DI 2048
#define NH 8
#define DKH 64
#define BSZ 32
#define MAXROWS (32*160)
#define MAXKV   (32*640)

// ---- fp32 scratch ----
__device__ float g_Q  [MAXROWS*DM];
__device__ float g_K  [MAXKV*DM];
__device__ float g_V  [MAXKV*DM];
__device__ float g_t0 [MAXROWS*DM];
__device__ float g_x  [MAXROWS*DM];

// ---- fp16 scratch ----
__device__ __align__(16) __half g_predh[MAXKV*DM];
__device__ __align__(16) __half g_enth [MAXROWS*DM];
__device__ __align__(16) __half g_ctxh [MAXROWS*DM];
__device__ __align__(16) __half g_xh   [MAXROWS*DM];
__device__ __align__(16) __half g_hh   [MAXROWS*DI];
__device__ __align__(16) __half g_wqh[DM*DM];
__device__ __align__(16) __half g_wkh[DM*DM];
__device__ __align__(16) __half g_wvh[DM*DM];
__device__ __align__(16) __half g_wfh[DM*DM];
__device__ __align__(16) __half g_w1h[DI*DM];
__device__ __align__(16) __half g_w2h[DM*DI];

__device__ __forceinline__ unsigned pack_h2(float a, float b) {
    __half2 t = __floats2half2_rn(a, b);
    return *(unsigned*)&t;
}

// ============================================================
// fp32 -> fp16 conversion (x4 vectorized)
// ============================================================
__global__ void cvt_h(const float* __restrict__ in, __half* __restrict__ out, int n4)
{
    int i = blockIdx.x * blockDim.x + threadIdx.x;
    if (i >= n4) return;
    float4 v = ((const float4*)in)[i];
    uint2 u;
    u.x = pack_h2(v.x, v.y);
    u.y = pack_h2(v.z, v.w);
    *(uint2*)(out + 4 * (size_t)i) = u;
}

// ============================================================
// Pipelined fp16 mma.sync GEMM: C[M,N] = A[M,K] @ W[N,K]^T + bias.
// Single fp16 pass, fp32 accum. 128x128 tile, BK=32, 256 thr,
// warp tile 64x32. 2-stage cp.async pipeline; rows padded to 80B.
// ============================================================
#define PBM 128
#define PBN 128
#define PBK 32
#define PLD 40
#define TILE_B (PBM*PLD*2)        // 10240 B per tile
#define STAGE_B (2*TILE_B)        // 20480 B per stage
#define GEMM_SMEM (2*STAGE_B)     // 40960 B dynamic

__device__ __forceinline__ unsigned smem_u32(const void* p) {
    return (unsigned)__cvta_generic_to_shared(p);
}
__device__ __forceinline__ void cp16(unsigned dst, const void* src, int sz) {
    asm volatile("cp.async.cg.shared.global [%0], [%1], 16, %2;"
        :: "r"(dst), "l"(src), "r"(sz) : "memory");
}
__device__ __forceinline__ void ldsm_x4(unsigned* r, const void* p) {
    unsigned a = smem_u32(p);
    asm volatile("ldmatrix.sync.aligned.m8n8.x4.shared.b16 {%0,%1,%2,%3}, [%4];"
        : "=r"(r[0]), "=r"(r[1]), "=r"(r[2]), "=r"(r[3]) : "r"(a));
}
__device__ __forceinline__ void ldsm_x2(unsigned* r, const void* p) {
    unsigned a = smem_u32(p);
    asm volatile("ldmatrix.sync.aligned.m8n8.x2.shared.b16 {%0,%1}, [%2];"
        : "=r"(r[0]), "=r"(r[1]) : "r"(a));
}
__device__ __forceinline__ void mma_h16(float* c, const unsigned* a, const unsigned* b) {
    asm volatile("mma.sync.aligned.m16n8k16.row.col.f32.f16.f16.f32 "
        "{%0,%1,%2,%3}, {%4,%5,%6,%7}, {%8,%9}, {%0,%1,%2,%3};"
        : "+f"(c[0]), "+f"(c[1]), "+f"(c[2]), "+f"(c[3])
        : "r"(a[0]), "r"(a[1]), "r"(a[2]), "r"(a[3]), "r"(b[0]), "r"(b[1]));
}

__global__ __launch_bounds__(256, 2)
void gemm_h(const __half* __restrict__ A, const int* __restrict__ rmap,
            const __half* __restrict__ W, const float* __restrict__ bias,
            float* __restrict__ Cf, __half* __restrict__ Ch,
            int M, int N, int K, int relu)
{
    extern __shared__ char sm[];
    __shared__ int irows[PBM];

    const int tid  = threadIdx.x;
    const int lane = tid & 31;
    const int wid  = tid >> 5;
    const int wm   = wid >> 2;
    const int wn   = wid & 3;
    const int bm = blockIdx.y * PBM;
    const int bn = blockIdx.x * PBN;

    if (tid < PBM) {
        int ar = bm + tid;
        irows[tid] = (ar < M) ? (rmap ? rmap[ar] : ar) : -1;
    }
    __syncthreads();

    const __half* srcs[2] = {A, W};

    float acc[4][4][4];
    #pragma unroll
    for (int mi = 0; mi < 4; ++mi) {
        #pragma unroll
        for (int ni = 0; ni < 4; ++ni) {
            #pragma unroll
            for (int j = 0; j < 4; ++j) acc[mi][ni][j] = 0.f;
        }
    }

    const unsigned smb = smem_u32(sm);
    const int nIter = K / PBK;

    // issue one stage's loads: 4 x 16B chunks per thread (1024 total)
    auto issue_stage = [&](int stage, int k0) {
        #pragma unroll
        for (int i = 0; i < 4; ++i) {
            int idx = tid + i * 256;      // 0..1023
            int buf = idx >> 9;           // 0=A, 1=W
            int j   = idx & 511;
            int r   = j >> 2;
            int c16 = j & 3;
            int grow;
            if (buf == 0) {
                grow = irows[r];
            } else {
                int wr = bn + r;
                grow = (wr < N) ? wr : -1;
            }
            unsigned dst = smb + stage * STAGE_B + buf * TILE_B + r * 80 + c16 * 16;
            const char* src = (const char*)srcs[buf]
                            + ((size_t)(grow < 0 ? 0 : grow) * K + k0) * 2 + c16 * 16;
            cp16(dst, src, grow >= 0 ? 16 : 0);
        }
        asm volatile("cp.async.commit_group;" ::: "memory");
    };

    issue_stage(0, 0);

    for (int c = 0; c < nIter; ++c) {
        if (c + 1 < nIter) {
            issue_stage((c + 1) & 1, (c + 1) * PBK);
            asm volatile("cp.async.wait_group 1;" ::: "memory");
        } else {
            asm volatile("cp.async.wait_group 0;" ::: "memory");
        }
        __syncthreads();

        char* st = sm + (c & 1) * STAGE_B;
        __half (*sA)[PLD] = (__half (*)[PLD])(st);
        __half (*sW)[PLD] = (__half (*)[PLD])(st + TILE_B);

        #pragma unroll
        for (int ks = 0; ks < 2; ++ks) {
            const int kk = ks * 16;
            unsigned av[4][4], bv[4][2];
            const int lr = lane & 15;
            const int lk = (lane >> 4) * 8;
            #pragma unroll
            for (int mi = 0; mi < 4; ++mi) {
                ldsm_x4(av[mi], &sA[wm * 64 + mi * 16 + lr][kk + lk]);
            }
            const int l8  = lane & 7;
            const int lk2 = ((lane >> 3) & 1) * 8;
            #pragma unroll
            for (int ni = 0; ni < 4; ++ni) {
                ldsm_x2(bv[ni], &sW[wn * 32 + ni * 8 + l8][kk + lk2]);
            }
            #pragma unroll
            for (int mi = 0; mi < 4; ++mi) {
                #pragma unroll
                for (int ni = 0; ni < 4; ++ni) {
                    mma_h16(acc[mi][ni], av[mi], bv[ni]);
                }
            }
        }
        __syncthreads();
    }

    // ---- epilogue ----
    #pragma unroll
    for (int mi = 0; mi < 4; ++mi) {
        int r0 = bm + wm * 64 + mi * 16 + (lane >> 2);
        #pragma unroll
        for (int ni = 0; ni < 4; ++ni) {
            int c = bn + wn * 32 + ni * 8 + (lane & 3) * 2;
            float b0 = bias[c];
            float b1 = bias[c + 1];
            float v0 = acc[mi][ni][0] + b0;
            float v1 = acc[mi][ni][1] + b1;
            float v2 = acc[mi][ni][2] + b0;
            float v3 = acc[mi][ni][3] + b1;
            if (relu) {
                v0 = fmaxf(v0, 0.f); v1 = fmaxf(v1, 0.f);
                v2 = fmaxf(v2, 0.f); v3 = fmaxf(v3, 0.f);
            }
            if (r0 < M) {
                size_t o = (size_t)r0 * N + c;
                if (Cf) *(float2*)(Cf + o) = make_float2(v0, v1);
                if (Ch) *(unsigned*)(Ch + o) = pack_h2(v0, v1);
            }
            if (r0 + 8 < M) {
                size_t o = (size_t)(r0 + 8) * N + c;
                if (Cf) *(float2*)(Cf + o) = make_float2(v2, v3);
                if (Ch) *(unsigned*)(Ch + o) = pack_h2(v2, v3);
            }
        }
    }
}

// ============================================================
// LayerNorm with residual; optional fp16 secondary output.
// ============================================================
__global__ void ln_res(const float* __restrict__ A, const float* __restrict__ R,
                       const int* __restrict__ rmap,
                       const float* __restrict__ g, const float* __restrict__ beta,
                       float* __restrict__ out, __half* __restrict__ outH)
{
    int row = blockIdx.x;
    int tid = threadIdx.x;   // 128
    __shared__ float red [128];
    __shared__ float red2[128];
    int rrow = rmap ? rmap[row] : row;
    float4 x = ((const float4*)(A + (size_t)row*DM))[tid];
    float4 r = ((const float4*)(R + (size_t)rrow*DM))[tid];
    x.x += r.x; x.y += r.y; x.z += r.z; x.w += r.w;
    red [tid] = x.x + x.y + x.z + x.w;
    red2[tid] = x.x*x.x + x.y*x.y + x.z*x.z + x.w*x.w;
    __syncthreads();
    #pragma unroll
    for (int o = 64; o > 0; o >>= 1) {
        if (tid < o) { red[tid] += red[tid+o]; red2[tid] += red2[tid+o]; }
        __syncthreads();
    }
    float mean = red[0] * (1.f/512.f);
    float var  = red2[0] * (1.f/512.f) - mean*mean;
    float inv  = rsqrtf(var + 1e-5f);
    float4 gg = ((const float4*)g)[tid];
    float4 bb = ((const float4*)beta)[tid];
    float4 o4;
    o4.x = (x.x - mean)*inv*gg.x + bb.x;
    o4.y = (x.y - mean)*inv*gg.y + bb.y;
    o4.z = (x.z - mean)*inv*gg.z + bb.z;
    o4.w = (x.w - mean)*inv*gg.w + bb.w;
    ((float4*)(out + (size_t)row*DM))[tid] = o4;
    if (outH) {
        size_t o = (size_t)row * DM + tid * 4;
        uint2 u;
        u.x = pack_h2(o4.x, o4.y);
        u.y = pack_h2(o4.z, o4.w);
        *(uint2*)(outH + o) = u;
    }
}

// ============================================================
// Flash-style attention; writes ctx as fp16.
// ============================================================
__global__ __launch_bounds__(128, 8)
void attn_flash(const float* __restrict__ Q, const float* __restrict__ Kb,
                const float* __restrict__ Vb, const int* __restrict__ mask,
                __half* __restrict__ ctxH, int Lq, int Lv)
{
    const int qt = blockIdx.x;
    const int h  = blockIdx.y;
    const int b  = blockIdx.z;
    const int t  = threadIdx.x;
    const int tq = t >> 3;
    const int kc = t & 7;
    const int q  = qt * 16 + tq;
    const bool qvalid = q < Lq;
    const int d0 = kc * 8;

    __shared__ float sQ[16][68];
    __shared__ float sK[32][68];
    __shared__ float sV[32][68];
    __shared__ float sP[16][36];

    #pragma unroll
    for (int i = 0; i < 2; ++i) {
        int idx = t + i * 128;
        int r  = idx >> 4;
        int c4 = idx & 15;
        int qq = qt * 16 + r;
        float4 v = make_float4(0.f, 0.f, 0.f, 0.f);
        if (qq < Lq) {
            v = *(const float4*)(Q + ((size_t)(b * Lq + qq)) * DM + h * DKH + c4 * 4);
        }
        *(float4*)&sQ[r][c4 * 4] = v;
    }

    float acc[8] = {0.f, 0.f, 0.f, 0.f, 0.f, 0.f, 0.f, 0.f};
    float m_run = -INFINITY;
    float l_run = 0.f;
    const int* mrow = mask + ((size_t)(b * Lq + (qvalid ? q : 0))) * Lv;

    for (int kv0 = 0; kv0 < Lv; kv0 += 32) {
        __syncthreads();
        #pragma unroll
        for (int i = 0; i < 4; ++i) {
            int idx = t + i * 128;
            int r  = idx >> 4;
            int c4 = idx & 15;
            int kv = kv0 + r;
            float4 kvv = make_float4(0.f, 0.f, 0.f, 0.f);
            float4 vvv = make_float4(0.f, 0.f, 0.f, 0.f);
            if (kv < Lv) {
                size_t base = ((size_t)(b * Lv + kv)) * DM + h * DKH + c4 * 4;
                kvv = *(const float4*)(Kb + base);
                vvv = *(const float4*)(Vb + base);
            }
            *(float4*)&sK[r][c4 * 4] = kvv;
            *(float4*)&sV[r][c4 * 4] = vvv;
        }
        __syncthreads();

        float s[4];
        #pragma unroll
        for (int c = 0; c < 4; ++c) {
            int k  = kc * 4 + c;
            int kv = kv0 + k;
            bool msk = true;
            if (qvalid && kv < Lv) {
                msk = (mrow[kv] != 0);
            }
            float a = 0.f;
            #pragma unroll
            for (int d4 = 0; d4 < 16; ++d4) {
                float4 qv = *(const float4*)&sQ[tq][d4 * 4];
                float4 kk = *(const float4*)&sK[k][d4 * 4];
                a += qv.x*kk.x + qv.y*kk.y + qv.z*kk.z + qv.w*kk.w;
            }
            s[c] = msk ? -INFINITY : a * 0.125f;
        }
        float tm = fmaxf(fmaxf(s[0], s[1]), fmaxf(s[2], s[3]));
        tm = fmaxf(tm, __shfl_xor_sync(0xffffffffu, tm, 1));
        tm = fmaxf(tm, __shfl_xor_sync(0xffffffffu, tm, 2));
        tm = fmaxf(tm, __shfl_xor_sync(0xffffffffu, tm, 4));
        float newm  = fmaxf(m_run, tm);
        float scale = __expf(fminf(m_run - newm, 0.f));
        float ts = 0.f;
        #pragma unroll
        for (int c = 0; c < 4; ++c) {
            float p = (s[c] == -INFINITY) ? 0.f : __expf(s[c] - newm);
            sP[tq][kc * 4 + c] = p;
            ts += p;
        }
        ts += __shfl_xor_sync(0xffffffffu, ts, 1);
        ts += __shfl_xor_sync(0xffffffffu, ts, 2);
        ts += __shfl_xor_sync(0xffffffffu, ts, 4);
        l_run = l_run * scale + ts;
        m_run = newm;
        #pragma unroll
        for (int j = 0; j < 8; ++j) acc[j] *= scale;
        __syncwarp();

        #pragma unroll 8
        for (int k = 0; k < 32; ++k) {
            float p = sP[tq][k];
            float4 v0 = *(const float4*)&sV[k][d0];
            float4 v1 = *(const float4*)&sV[k][d0 + 4];
            acc[0] += p * v0.x; acc[1] += p * v0.y; acc[2] += p * v0.z; acc[3] += p * v0.w;
            acc[4] += p * v1.x; acc[5] += p * v1.y; acc[6] += p * v1.z; acc[7] += p * v1.w;
        }
    }

    if (qvalid) {
        float inv = 1.f / l_run;
        float o[8];
        #pragma unroll
        for (int j = 0; j < 8; ++j) o[j] = acc[j] * inv;
        size_t off = ((size_t)(b * Lq + q)) * DM + h * DKH + d0;
        uint4 u;
        u.x = pack_h2(o[0], o[1]); u.y = pack_h2(o[2], o[3]);
        u.z = pack_h2(o[4], o[5]); u.w = pack_h2(o[6], o[7]);
        *(uint4*)(ctxH + off) = u;
    }
}

// ============================================================
// launcher
// ============================================================
extern "C" void kernel_launch(void* const* d_in, const int* in_sizes, int n_in,
                              void* d_out, int out_size)
{
    const float* ent   = (const float*)d_in[0];
    const float* pred  = (const float*)d_in[1];
    const float* w_qs  = (const float*)d_in[2];
    const float* b_qs  = (const float*)d_in[3];
    const float* w_ks  = (const float*)d_in[4];
    const float* b_ks  = (const float*)d_in[5];
    const float* w_vs  = (const float*)d_in[6];
    const float* b_vs  = (const float*)d_in[7];
    const float* w_fc  = (const float*)d_in[8];
    const float* b_fc  = (const float*)d_in[9];
    const float* ln1_g = (const float*)d_in[10];
    const float* ln1_b = (const float*)d_in[11];
    const float* w1    = (const float*)d_in[12];
    const float* b1    = (const float*)d_in[13];
    const float* w2    = (const float*)d_in[14];
    const float* b2    = (const float*)d_in[15];
    const float* ln2_g = (const float*)d_in[16];
    const float* ln2_b = (const float*)d_in[17];
    const int*   amask = (const int*)d_in[18];
    const int*   gidx  = (const int*)d_in[20];

    int Lq  = in_sizes[0] / (BSZ * DM);
    int Lv  = in_sizes[1] / (BSZ * DM);
    int nv  = in_sizes[20];
    int MKV = BSZ * Lv;
    int MQ  = BSZ * Lq;

    float *pQ, *pK, *pV, *pT0, *pX;
    cudaGetSymbolAddress((void**)&pQ,  g_Q);
    cudaGetSymbolAddress((void**)&pK,  g_K);
    cudaGetSymbolAddress((void**)&pV,  g_V);
    cudaGetSymbolAddress((void**)&pT0, g_t0);
    cudaGetSymbolAddress((void**)&pX,  g_x);

    __half *predh, *enth, *ctxh, *xh, *hh;
    __half *wqh, *wkh, *wvh, *wfh, *w1h, *w2h;
    cudaGetSymbolAddress((void**)&predh, g_predh);
    cudaGetSymbolAddress((void**)&enth,  g_enth);
    cudaGetSymbolAddress((void**)&ctxh,  g_ctxh);
    cudaGetSymbolAddress((void**)&xh,    g_xh);
    cudaGetSymbolAddress((void**)&hh,    g_hh);
    cudaGetSymbolAddress((void**)&wqh,   g_wqh);
    cudaGetSymbolAddress((void**)&wkh,   g_wkh);
    cudaGetSymbolAddress((void**)&wvh,   g_wvh);
    cudaGetSymbolAddress((void**)&wfh,   g_wfh);
    cudaGetSymbolAddress((void**)&w1h,   g_w1h);
    cudaGetSymbolAddress((void**)&w2h,   g_w2h);

    cudaFuncSetAttribute(gemm_h, cudaFuncAttributeMaxDynamicSharedMemorySize, GEMM_SMEM);

    int n4;
    n4 = MKV * DM / 4;  cvt_h<<<(n4 + 255) / 256, 256>>>(pred, predh, n4);
    n4 = DM * DM / 4;   cvt_h<<<(n4 + 255) / 256, 256>>>(w_ks, wkh, n4);
    n4 = DM * DM / 4;   cvt_h<<<(n4 + 255) / 256, 256>>>(w_vs, wvh, n4);
    n4 = MQ * DM / 4;   cvt_h<<<(n4 + 255) / 256, 256>>>(ent, enth, n4);
    n4 = DM * DM / 4;   cvt_h<<<(n4 + 255) / 256, 256>>>(w_qs, wqh, n4);

    // K, V, Q projections (launch #5 = K GEMM for ncu -s 5)
    {
        dim3 grd(DM / PBN, (MKV + PBM - 1) / PBM);
        gemm_h<<<grd, 256, GEMM_SMEM>>>(predh, nullptr, wkh, b_ks,
                                        pK, nullptr, MKV, DM, DM, 0);
        gemm_h<<<grd, 256, GEMM_SMEM>>>(predh, nullptr, wvh, b_vs,
                                        pV, nullptr, MKV, DM, DM, 0);
    }
    {
        dim3 grd(DM / PBN, (MQ + PBM - 1) / PBM);
        gemm_h<<<grd, 256, GEMM_SMEM>>>(enth, nullptr, wqh, b_qs,
                                        pQ, nullptr, MQ, DM, DM, 0);
    }
    // attention -> ctx (fp16, padded)
    {
        dim3 grd((Lq + 15) / 16, NH, BSZ);
        attn_flash<<<grd, 128>>>(pQ, pK, pV, amask, ctxh, Lq, Lv);
    }
    // fc projection (gathers valid rows) + LN1
    n4 = DM * DM / 4;   cvt_h<<<(n4 + 255) / 256, 256>>>(w_fc, wfh, n4);
    {
        dim3 grd(DM / PBN, (nv + PBM - 1) / PBM);
        gemm_h<<<grd, 256, GEMM_SMEM>>>(ctxh, gidx, wfh, b_fc,
                                        pT0, nullptr, nv, DM, DM, 0);
        ln_res<<<nv, 128>>>(pT0, ent, gidx, ln1_g, ln1_b, pX, xh);
    }
    // FFN
    n4 = DI * DM / 4;   cvt_h<<<(n4 + 255) / 256, 256>>>(w1, w1h, n4);
    {
        dim3 grd(DI / PBN, (nv + PBM - 1) / PBM);
        gemm_h<<<grd, 256, GEMM_SMEM>>>(xh, nullptr, w1h, b1,
                                        nullptr, hh, nv, DI, DM, 1);
    }
    n4 = DM * DI / 4;   cvt_h<<<(n4 + 255) / 256, 256>>>(w2, w2h, n4);
    {
        dim3 grd(DM / PBN, (nv + PBM - 1) / PBM);
        gemm_h<<<grd, 256, GEMM_SMEM>>>(hh, nullptr, w2h, b2,
                                        pT0, nullptr, nv, DM, DI, 0);
        ln_res<<<nv, 128>>>(pT0, pX, nullptr, ln2_g, ln2_b, (float*)d_out, nullptr);
    }
}

// round 11
// speedup vs baseline: 1.3670x; 1.0103x over previous
#include <cuda_runtime.h>
#include <cuda_fp16.h>
#include <cstdint>
#include <math.h>

#define DM 512
#define DI 2048
#define NH 8
#define DKH 64
#define BSZ 32
#define MAXROWS (32*160)
#define MAXKV   (32*640)

// ---- fp32 scratch ----
__device__ float g_Q  [MAXROWS*DM];
__device__ float g_K  [MAXKV*DM];
__device__ float g_V  [MAXKV*DM];
__device__ float g_t0 [MAXROWS*DM];
__device__ float g_x  [MAXROWS*DM];

// ---- fp16 scratch ----
__device__ __align__(16) __half g_predh[MAXKV*DM];
__device__ __align__(16) __half g_enth [MAXROWS*DM];
__device__ __align__(16) __half g_ctxh [MAXROWS*DM];
__device__ __align__(16) __half g_xh   [MAXROWS*DM];
__device__ __align__(16) __half g_hh   [MAXROWS*DI];
__device__ __align__(16) __half g_wqh[DM*DM];
__device__ __align__(16) __half g_wkh[DM*DM];
__device__ __align__(16) __half g_wvh[DM*DM];
__device__ __align__(16) __half g_wfh[DM*DM];
__device__ __align__(16) __half g_w1h[DI*DM];
__device__ __align__(16) __half g_w2h[DM*DI];

__device__ __forceinline__ unsigned pack_h2(float a, float b) {
    __half2 t = __floats2half2_rn(a, b);
    return *(unsigned*)&t;
}

// ============================================================
// Fused fp32 -> fp16 conversion over 8 segments, ONE launch.
// ============================================================
struct CvtArgs {
    const float4* src[8];
    uint2*        dst[8];
    int           off[9];   // prefix sums in float4 units
};

__global__ void cvt_all(CvtArgs a)
{
    int i = blockIdx.x * blockDim.x + threadIdx.x;
    if (i >= a.off[8]) return;
    int s = 0;
    #pragma unroll
    for (int k = 1; k < 8; ++k) {
        if (i >= a.off[k]) s = k;
    }
    int local = i - a.off[s];
    float4 v = a.src[s][local];
    uint2 u;
    u.x = pack_h2(v.x, v.y);
    u.y = pack_h2(v.z, v.w);
    a.dst[s][local] = u;
}

// ============================================================
// 3-stage pipelined fp16 mma.sync GEMM, single __syncthreads/iter.
// C[M,N] = A[M,K] @ W[N,K]^T + bias. fp32 accum.
// 128x128 tile, BK=32, 256 thr, warp tile 64x32, rows padded 80B.
// ============================================================
#define PBM 128
#define PBN 128
#define PBK 32
#define PLD 40
#define TILE_B (PBM*PLD*2)        // 10240 B per tile
#define STAGE_B (2*TILE_B)        // 20480 B per stage
#define NSTAGE 3
#define GEMM_SMEM (NSTAGE*STAGE_B)  // 61440 B dynamic

__device__ __forceinline__ unsigned smem_u32(const void* p) {
    return (unsigned)__cvta_generic_to_shared(p);
}
__device__ __forceinline__ void cp16(unsigned dst, const void* src, int sz) {
    asm volatile("cp.async.cg.shared.global [%0], [%1], 16, %2;"
        :: "r"(dst), "l"(src), "r"(sz) : "memory");
}
__device__ __forceinline__ void ldsm_x4(unsigned* r, const void* p) {
    unsigned a = smem_u32(p);
    asm volatile("ldmatrix.sync.aligned.m8n8.x4.shared.b16 {%0,%1,%2,%3}, [%4];"
        : "=r"(r[0]), "=r"(r[1]), "=r"(r[2]), "=r"(r[3]) : "r"(a));
}
__device__ __forceinline__ void ldsm_x2(unsigned* r, const void* p) {
    unsigned a = smem_u32(p);
    asm volatile("ldmatrix.sync.aligned.m8n8.x2.shared.b16 {%0,%1}, [%2];"
        : "=r"(r[0]), "=r"(r[1]) : "r"(a));
}
__device__ __forceinline__ void mma_h16(float* c, const unsigned* a, const unsigned* b) {
    asm volatile("mma.sync.aligned.m16n8k16.row.col.f32.f16.f16.f32 "
        "{%0,%1,%2,%3}, {%4,%5,%6,%7}, {%8,%9}, {%0,%1,%2,%3};"
        : "+f"(c[0]), "+f"(c[1]), "+f"(c[2]), "+f"(c[3])
        : "r"(a[0]), "r"(a[1]), "r"(a[2]), "r"(a[3]), "r"(b[0]), "r"(b[1]));
}

__global__ __launch_bounds__(256, 2)
void gemm_h(const __half* __restrict__ A, const int* __restrict__ rmap,
            const __half* __restrict__ W, const float* __restrict__ bias,
            float* __restrict__ Cf, __half* __restrict__ Ch,
            int M, int N, int K, int relu)
{
    extern __shared__ char sm[];
    __shared__ int irows[PBM];

    const int tid  = threadIdx.x;
    const int lane = tid & 31;
    const int wid  = tid >> 5;
    const int wm   = wid >> 2;
    const int wn   = wid & 3;
    const int bm = blockIdx.y * PBM;
    const int bn = blockIdx.x * PBN;

    if (tid < PBM) {
        int ar = bm + tid;
        irows[tid] = (ar < M) ? (rmap ? rmap[ar] : ar) : -1;
    }
    __syncthreads();

    const __half* srcs[2] = {A, W};

    float acc[4][4][4];
    #pragma unroll
    for (int mi = 0; mi < 4; ++mi) {
        #pragma unroll
        for (int ni = 0; ni < 4; ++ni) {
            #pragma unroll
            for (int j = 0; j < 4; ++j) acc[mi][ni][j] = 0.f;
        }
    }

    const unsigned smb = smem_u32(sm);
    const int nIter = K / PBK;

    // issue one k-block's loads: 4 x 16B chunks per thread (1024 total)
    auto issue_stage = [&](int stage, int k0) {
        #pragma unroll
        for (int i = 0; i < 4; ++i) {
            int idx = tid + i * 256;      // 0..1023
            int buf = idx >> 9;           // 0=A, 1=W
            int j   = idx & 511;
            int r   = j >> 2;
            int c16 = j & 3;
            int grow;
            if (buf == 0) {
                grow = irows[r];
            } else {
                int wr = bn + r;
                grow = (wr < N) ? wr : -1;
            }
            unsigned dst = smb + stage * STAGE_B + buf * TILE_B + r * 80 + c16 * 16;
            const char* src = (const char*)srcs[buf]
                            + ((size_t)(grow < 0 ? 0 : grow) * K + k0) * 2 + c16 * 16;
            cp16(dst, src, grow >= 0 ? 16 : 0);
        }
        asm volatile("cp.async.commit_group;" ::: "memory");
    };

    // prologue: blocks 0,1 in flight
    issue_stage(0, 0);
    issue_stage(1, PBK);

    for (int c = 0; c < nIter; ++c) {
        if (c < nIter - 1) {
            asm volatile("cp.async.wait_group 1;" ::: "memory");
        } else {
            asm volatile("cp.async.wait_group 0;" ::: "memory");
        }
        __syncthreads();   // block c visible; all threads done reading buffer (c+2)%3

        if (c + 2 < nIter) {
            int nb = c + 2;
            int st = nb - (nb / NSTAGE) * NSTAGE;
            issue_stage(st, nb * PBK);
        }

        int cs = c - (c / NSTAGE) * NSTAGE;
        char* st = sm + cs * STAGE_B;
        __half (*sA)[PLD] = (__half (*)[PLD])(st);
        __half (*sW)[PLD] = (__half (*)[PLD])(st + TILE_B);

        #pragma unroll
        for (int ks = 0; ks < 2; ++ks) {
            const int kk = ks * 16;
            unsigned av[4][4], bv[4][2];
            const int lr = lane & 15;
            const int lk = (lane >> 4) * 8;
            #pragma unroll
            for (int mi = 0; mi < 4; ++mi) {
                ldsm_x4(av[mi], &sA[wm * 64 + mi * 16 + lr][kk + lk]);
            }
            const int l8  = lane & 7;
            const int lk2 = ((lane >> 3) & 1) * 8;
            #pragma unroll
            for (int ni = 0; ni < 4; ++ni) {
                ldsm_x2(bv[ni], &sW[wn * 32 + ni * 8 + l8][kk + lk2]);
            }
            #pragma unroll
            for (int mi = 0; mi < 4; ++mi) {
                #pragma unroll
                for (int ni = 0; ni < 4; ++ni) {
                    mma_h16(acc[mi][ni], av[mi], bv[ni]);
                }
            }
        }
    }

    // ---- epilogue ----
    #pragma unroll
    for (int mi = 0; mi < 4; ++mi) {
        int r0 = bm + wm * 64 + mi * 16 + (lane >> 2);
        #pragma unroll
        for (int ni = 0; ni < 4; ++ni) {
            int c = bn + wn * 32 + ni * 8 + (lane & 3) * 2;
            float b0 = bias[c];
            float b1 = bias[c + 1];
            float v0 = acc[mi][ni][0] + b0;
            float v1 = acc[mi][ni][1] + b1;
            float v2 = acc[mi][ni][2] + b0;
            float v3 = acc[mi][ni][3] + b1;
            if (relu) {
                v0 = fmaxf(v0, 0.f); v1 = fmaxf(v1, 0.f);
                v2 = fmaxf(v2, 0.f); v3 = fmaxf(v3, 0.f);
            }
            if (r0 < M) {
                size_t o = (size_t)r0 * N + c;
                if (Cf) *(float2*)(Cf + o) = make_float2(v0, v1);
                if (Ch) *(unsigned*)(Ch + o) = pack_h2(v0, v1);
            }
            if (r0 + 8 < M) {
                size_t o = (size_t)(r0 + 8) * N + c;
                if (Cf) *(float2*)(Cf + o) = make_float2(v2, v3);
                if (Ch) *(unsigned*)(Ch + o) = pack_h2(v2, v3);
            }
        }
    }
}

// ============================================================
// LayerNorm with residual; optional fp16 secondary output.
// ============================================================
__global__ void ln_res(const float* __restrict__ A, const float* __restrict__ R,
                       const int* __restrict__ rmap,
                       const float* __restrict__ g, const float* __restrict__ beta,
                       float* __restrict__ out, __half* __restrict__ outH)
{
    int row = blockIdx.x;
    int tid = threadIdx.x;   // 128
    __shared__ float red [128];
    __shared__ float red2[128];
    int rrow = rmap ? rmap[row] : row;
    float4 x = ((const float4*)(A + (size_t)row*DM))[tid];
    float4 r = ((const float4*)(R + (size_t)rrow*DM))[tid];
    x.x += r.x; x.y += r.y; x.z += r.z; x.w += r.w;
    red [tid] = x.x + x.y + x.z + x.w;
    red2[tid] = x.x*x.x + x.y*x.y + x.z*x.z + x.w*x.w;
    __syncthreads();
    #pragma unroll
    for (int o = 64; o > 0; o >>= 1) {
        if (tid < o) { red[tid] += red[tid+o]; red2[tid] += red2[tid+o]; }
        __syncthreads();
    }
    float mean = red[0] * (1.f/512.f);
    float var  = red2[0] * (1.f/512.f) - mean*mean;
    float inv  = rsqrtf(var + 1e-5f);
    float4 gg = ((const float4*)g)[tid];
    float4 bb = ((const float4*)beta)[tid];
    float4 o4;
    o4.x = (x.x - mean)*inv*gg.x + bb.x;
    o4.y = (x.y - mean)*inv*gg.y + bb.y;
    o4.z = (x.z - mean)*inv*gg.z + bb.z;
    o4.w = (x.w - mean)*inv*gg.w + bb.w;
    ((float4*)(out + (size_t)row*DM))[tid] = o4;
    if (outH) {
        size_t o = (size_t)row * DM + tid * 4;
        uint2 u;
        u.x = pack_h2(o4.x, o4.y);
        u.y = pack_h2(o4.z, o4.w);
        *(uint2*)(outH + o) = u;
    }
}

// ============================================================
// Flash-style attention; writes ctx as fp16.
// ============================================================
__global__ __launch_bounds__(128, 8)
void attn_flash(const float* __restrict__ Q, const float* __restrict__ Kb,
                const float* __restrict__ Vb, const int* __restrict__ mask,
                __half* __restrict__ ctxH, int Lq, int Lv)
{
    const int qt = blockIdx.x;
    const int h  = blockIdx.y;
    const int b  = blockIdx.z;
    const int t  = threadIdx.x;
    const int tq = t >> 3;
    const int kc = t & 7;
    const int q  = qt * 16 + tq;
    const bool qvalid = q < Lq;
    const int d0 = kc * 8;

    __shared__ float sQ[16][68];
    __shared__ float sK[32][68];
    __shared__ float sV[32][68];
    __shared__ float sP[16][36];

    #pragma unroll
    for (int i = 0; i < 2; ++i) {
        int idx = t + i * 128;
        int r  = idx >> 4;
        int c4 = idx & 15;
        int qq = qt * 16 + r;
        float4 v = make_float4(0.f, 0.f, 0.f, 0.f);
        if (qq < Lq) {
            v = *(const float4*)(Q + ((size_t)(b * Lq + qq)) * DM + h * DKH + c4 * 4);
        }
        *(float4*)&sQ[r][c4 * 4] = v;
    }

    float acc[8] = {0.f, 0.f, 0.f, 0.f, 0.f, 0.f, 0.f, 0.f};
    float m_run = -INFINITY;
    float l_run = 0.f;
    const int* mrow = mask + ((size_t)(b * Lq + (qvalid ? q : 0))) * Lv;

    for (int kv0 = 0; kv0 < Lv; kv0 += 32) {
        __syncthreads();
        #pragma unroll
        for (int i = 0; i < 4; ++i) {
            int idx = t + i * 128;
            int r  = idx >> 4;
            int c4 = idx & 15;
            int kv = kv0 + r;
            float4 kvv = make_float4(0.f, 0.f, 0.f, 0.f);
            float4 vvv = make_float4(0.f, 0.f, 0.f, 0.f);
            if (kv < Lv) {
                size_t base = ((size_t)(b * Lv + kv)) * DM + h * DKH + c4 * 4;
                kvv = *(const float4*)(Kb + base);
                vvv = *(const float4*)(Vb + base);
            }
            *(float4*)&sK[r][c4 * 4] = kvv;
            *(float4*)&sV[r][c4 * 4] = vvv;
        }
        __syncthreads();

        float s[4];
        #pragma unroll
        for (int c = 0; c < 4; ++c) {
            int k  = kc * 4 + c;
            int kv = kv0 + k;
            bool msk = true;
            if (qvalid && kv < Lv) {
                msk = (mrow[kv] != 0);
            }
            float a = 0.f;
            #pragma unroll
            for (int d4 = 0; d4 < 16; ++d4) {
                float4 qv = *(const float4*)&sQ[tq][d4 * 4];
                float4 kk = *(const float4*)&sK[k][d4 * 4];
                a += qv.x*kk.x + qv.y*kk.y + qv.z*kk.z + qv.w*kk.w;
            }
            s[c] = msk ? -INFINITY : a * 0.125f;
        }
        float tm = fmaxf(fmaxf(s[0], s[1]), fmaxf(s[2], s[3]));
        tm = fmaxf(tm, __shfl_xor_sync(0xffffffffu, tm, 1));
        tm = fmaxf(tm, __shfl_xor_sync(0xffffffffu, tm, 2));
        tm = fmaxf(tm, __shfl_xor_sync(0xffffffffu, tm, 4));
        float newm  = fmaxf(m_run, tm);
        float scale = __expf(fminf(m_run - newm, 0.f));
        float ts = 0.f;
        #pragma unroll
        for (int c = 0; c < 4; ++c) {
            float p = (s[c] == -INFINITY) ? 0.f : __expf(s[c] - newm);
            sP[tq][kc * 4 + c] = p;
            ts += p;
        }
        ts += __shfl_xor_sync(0xffffffffu, ts, 1);
        ts += __shfl_xor_sync(0xffffffffu, ts, 2);
        ts += __shfl_xor_sync(0xffffffffu, ts, 4);
        l_run = l_run * scale + ts;
        m_run = newm;
        #pragma unroll
        for (int j = 0; j < 8; ++j) acc[j] *= scale;
        __syncwarp();

        #pragma unroll 8
        for (int k = 0; k < 32; ++k) {
            float p = sP[tq][k];
            float4 v0 = *(const float4*)&sV[k][d0];
            float4 v1 = *(const float4*)&sV[k][d0 + 4];
            acc[0] += p * v0.x; acc[1] += p * v0.y; acc[2] += p * v0.z; acc[3] += p * v0.w;
            acc[4] += p * v1.x; acc[5] += p * v1.y; acc[6] += p * v1.z; acc[7] += p * v1.w;
        }
    }

    if (qvalid) {
        float inv = 1.f / l_run;
        float o[8];
        #pragma unroll
        for (int j = 0; j < 8; ++j) o[j] = acc[j] * inv;
        size_t off = ((size_t)(b * Lq + q)) * DM + h * DKH + d0;
        uint4 u;
        u.x = pack_h2(o[0], o[1]); u.y = pack_h2(o[2], o[3]);
        u.z = pack_h2(o[4], o[5]); u.w = pack_h2(o[6], o[7]);
        *(uint4*)(ctxH + off) = u;
    }
}

// ============================================================
// launcher
// ============================================================
extern "C" void kernel_launch(void* const* d_in, const int* in_sizes, int n_in,
                              void* d_out, int out_size)
{
    const float* ent   = (const float*)d_in[0];
    const float* pred  = (const float*)d_in[1];
    const float* w_qs  = (const float*)d_in[2];
    const float* b_qs  = (const float*)d_in[3];
    const float* w_ks  = (const float*)d_in[4];
    const float* b_ks  = (const float*)d_in[5];
    const float* w_vs  = (const float*)d_in[6];
    const float* b_vs  = (const float*)d_in[7];
    const float* w_fc  = (const float*)d_in[8];
    const float* b_fc  = (const float*)d_in[9];
    const float* ln1_g = (const float*)d_in[10];
    const float* ln1_b = (const float*)d_in[11];
    const float* w1    = (const float*)d_in[12];
    const float* b1    = (const float*)d_in[13];
    const float* w2    = (const float*)d_in[14];
    const float* b2    = (const float*)d_in[15];
    const float* ln2_g = (const float*)d_in[16];
    const float* ln2_b = (const float*)d_in[17];
    const int*   amask = (const int*)d_in[18];
    const int*   gidx  = (const int*)d_in[20];

    int Lq  = in_sizes[0] / (BSZ * DM);
    int Lv  = in_sizes[1] / (BSZ * DM);
    int nv  = in_sizes[20];
    int MKV = BSZ * Lv;
    int MQ  = BSZ * Lq;

    float *pQ, *pK, *pV, *pT0, *pX;
    cudaGetSymbolAddress((void**)&pQ,  g_Q);
    cudaGetSymbolAddress((void**)&pK,  g_K);
    cudaGetSymbolAddress((void**)&pV,  g_V);
    cudaGetSymbolAddress((void**)&pT0, g_t0);
    cudaGetSymbolAddress((void**)&pX,  g_x);

    __half *predh, *enth, *ctxh, *xh, *hh;
    __half *wqh, *wkh, *wvh, *wfh, *w1h, *w2h;
    cudaGetSymbolAddress((void**)&predh, g_predh);
    cudaGetSymbolAddress((void**)&enth,  g_enth);
    cudaGetSymbolAddress((void**)&ctxh,  g_ctxh);
    cudaGetSymbolAddress((void**)&xh,    g_xh);
    cudaGetSymbolAddress((void**)&hh,    g_hh);
    cudaGetSymbolAddress((void**)&wqh,   g_wqh);
    cudaGetSymbolAddress((void**)&wkh,   g_wkh);
    cudaGetSymbolAddress((void**)&wvh,   g_wvh);
    cudaGetSymbolAddress((void**)&wfh,   g_wfh);
    cudaGetSymbolAddress((void**)&w1h,   g_w1h);
    cudaGetSymbolAddress((void**)&w2h,   g_w2h);

    cudaFuncSetAttribute(gemm_h, cudaFuncAttributeMaxDynamicSharedMemorySize, GEMM_SMEM);

    // ---- launch 0: all conversions fused ----
    {
        CvtArgs a;
        const float* s[8] = {pred, ent, w_qs, w_ks, w_vs, w_fc, w1, w2};
        __half*      d[8] = {predh, enth, wqh, wkh, wvh, wfh, w1h, w2h};
        int len4[8] = {MKV*DM/4, MQ*DM/4, DM*DM/4, DM*DM/4, DM*DM/4, DM*DM/4,
                       DI*DM/4, DM*DI/4};
        int acc = 0;
        for (int i = 0; i < 8; ++i) {
            a.src[i] = (const float4*)s[i];
            a.dst[i] = (uint2*)d[i];
            a.off[i] = acc;
            acc += len4[i];
        }
        a.off[8] = acc;
        cvt_all<<<(acc + 255) / 256, 256>>>(a);
    }

    // launch 1: Q gemm; 2: K gemm; 3: V gemm (profiler targets at idx 3/5)
    {
        dim3 grd(DM / PBN, (MQ + PBM - 1) / PBM);
        gemm_h<<<grd, 256, GEMM_SMEM>>>(enth, nullptr, wqh, b_qs,
                                        pQ, nullptr, MQ, DM, DM, 0);
    }
    {
        dim3 grd(DM / PBN, (MKV + PBM - 1) / PBM);
        gemm_h<<<grd, 256, GEMM_SMEM>>>(predh, nullptr, wkh, b_ks,
                                        pK, nullptr, MKV, DM, DM, 0);
        gemm_h<<<grd, 256, GEMM_SMEM>>>(predh, nullptr, wvh, b_vs,
                                        pV, nullptr, MKV, DM, DM, 0);
    }
    // launch 4: attention
    {
        dim3 grd((Lq + 15) / 16, NH, BSZ);
        attn_flash<<<grd, 128>>>(pQ, pK, pV, amask, ctxh, Lq, Lv);
    }
    // launch 5: fc gemm (gathers valid rows); 6: ln1
    {
        dim3 grd(DM / PBN, (nv + PBM - 1) / PBM);
        gemm_h<<<grd, 256, GEMM_SMEM>>>(ctxh, gidx, wfh, b_fc,
                                        pT0, nullptr, nv, DM, DM, 0);
        ln_res<<<nv, 128>>>(pT0, ent, gidx, ln1_g, ln1_b, pX, xh);
    }
    // launches 7-9: FFN + ln2
    {
        dim3 grd(DI / PBN, (nv + PBM - 1) / PBM);
        gemm_h<<<grd, 256, GEMM_SMEM>>>(xh, nullptr, w1h, b1,
                                        nullptr, hh, nv, DI, DM, 1);
    }
    {
        dim3 grd(DM / PBN, (nv + PBM - 1) / PBM);
        gemm_h<<<grd, 256, GEMM_SMEM>>>(hh, nullptr, w2h, b2,
                                        pT0, nullptr, nv, DM, DI, 0);
        ln_res<<<nv, 128>>>(pT0, pX, nullptr, ln2_g, ln2_b, (float*)d_out, nullptr);
    }
}

// round 15
// speedup vs baseline: 5.2940x; 3.8726x over previous
#include <cuda_runtime.h>
#include <cuda_fp16.h>
#include <cstdint>
#include <math.h>

#define DM 512
#define DI 2048
#define NH 8
#define DKH 64
#define BSZ 32
#define MAXROWS (32*160)
#define MAXKV   (32*640)

// ---- fp32 scratch ----
__device__ float g_t0 [MAXROWS*DM];
__device__ float g_x  [MAXROWS*DM];

// ---- fp16 scratch ----
__device__ __align__(16) __half g_predh[MAXKV*DM];
__device__ __align__(16) __half g_enth [MAXROWS*DM];
__device__ __align__(16) __half g_qh   [MAXROWS*DM];
__device__ __align__(16) __half g_kh   [MAXKV*DM];
__device__ __align__(16) __half g_vh   [MAXKV*DM];
__device__ __align__(16) __half g_ctxh [MAXROWS*DM];
__device__ __align__(16) __half g_xh   [MAXROWS*DM];
__device__ __align__(16) __half g_hh   [MAXROWS*DI];
__device__ __align__(16) __half g_wqh[DM*DM];
__device__ __align__(16) __half g_wkh[DM*DM];
__device__ __align__(16) __half g_wvh[DM*DM];
__device__ __align__(16) __half g_wfh[DM*DM];
__device__ __align__(16) __half g_w1h[DI*DM];
__device__ __align__(16) __half g_w2h[DM*DI];

__device__ __forceinline__ unsigned pack_h2(float a, float b) {
    __half2 t = __floats2half2_rn(a, b);
    return *(unsigned*)&t;
}

// ============================================================
// Fused fp32 -> fp16 conversion over 8 segments, ONE launch.
// ============================================================
struct CvtArgs {
    const float4* src[8];
    uint2*        dst[8];
    int           off[9];
};

__global__ void cvt_all(CvtArgs a)
{
    int i = blockIdx.x * blockDim.x + threadIdx.x;
    if (i >= a.off[8]) return;
    int s = 0;
    #pragma unroll
    for (int k = 1; k < 8; ++k) {
        if (i >= a.off[k]) s = k;
    }
    int local = i - a.off[s];
    float4 v = a.src[s][local];
    uint2 u;
    u.x = pack_h2(v.x, v.y);
    u.y = pack_h2(v.z, v.w);
    a.dst[s][local] = u;
}

// ============================================================
// shared helpers
// ============================================================
__device__ __forceinline__ unsigned smem_u32(const void* p) {
    return (unsigned)__cvta_generic_to_shared(p);
}
__device__ __forceinline__ void cp16(unsigned dst, const void* src, int sz) {
    asm volatile("cp.async.cg.shared.global [%0], [%1], 16, %2;"
        :: "r"(dst), "l"(src), "r"(sz) : "memory");
}
__device__ __forceinline__ void ldsm_x4(unsigned* r, const void* p) {
    unsigned a = smem_u32(p);
    asm volatile("ldmatrix.sync.aligned.m8n8.x4.shared.b16 {%0,%1,%2,%3}, [%4];"
        : "=r"(r[0]), "=r"(r[1]), "=r"(r[2]), "=r"(r[3]) : "r"(a));
}
__device__ __forceinline__ void ldsm_x2(unsigned* r, const void* p) {
    unsigned a = smem_u32(p);
    asm volatile("ldmatrix.sync.aligned.m8n8.x2.shared.b16 {%0,%1}, [%2];"
        : "=r"(r[0]), "=r"(r[1]) : "r"(a));
}
__device__ __forceinline__ void mma_h16(float* c, const unsigned* a, const unsigned* b) {
    asm volatile("mma.sync.aligned.m16n8k16.row.col.f32.f16.f16.f32 "
        "{%0,%1,%2,%3}, {%4,%5,%6,%7}, {%8,%9}, {%0,%1,%2,%3};"
        : "+f"(c[0]), "+f"(c[1]), "+f"(c[2]), "+f"(c[3])
        : "r"(a[0]), "r"(a[1]), "r"(a[2]), "r"(a[3]), "r"(b[0]), "r"(b[1]));
}

// ============================================================
// 3-stage pipelined fp16 mma.sync GEMM (passing since R11).
// ============================================================
#define PBM 128
#define PBN 128
#define PBK 32
#define PLD 40
#define TILE_B (PBM*PLD*2)
#define STAGE_B (2*TILE_B)
#define NSTAGE 3
#define GEMM_SMEM (NSTAGE*STAGE_B)

__global__ __launch_bounds__(256, 2)
void gemm_h(const __half* __restrict__ A, const int* __restrict__ rmap,
            const __half* __restrict__ W, const float* __restrict__ bias,
            float* __restrict__ Cf, __half* __restrict__ Ch,
            int M, int N, int K, int relu)
{
    extern __shared__ char sm[];
    __shared__ int irows[PBM];

    const int tid  = threadIdx.x;
    const int lane = tid & 31;
    const int wid  = tid >> 5;
    const int wm   = wid >> 2;
    const int wn   = wid & 3;
    const int bm = blockIdx.y * PBM;
    const int bn = blockIdx.x * PBN;

    if (tid < PBM) {
        int ar = bm + tid;
        irows[tid] = (ar < M) ? (rmap ? rmap[ar] : ar) : -1;
    }
    __syncthreads();

    const __half* srcs[2] = {A, W};

    float acc[4][4][4];
    #pragma unroll
    for (int mi = 0; mi < 4; ++mi) {
        #pragma unroll
        for (int ni = 0; ni < 4; ++ni) {
            #pragma unroll
            for (int j = 0; j < 4; ++j) acc[mi][ni][j] = 0.f;
        }
    }

    const unsigned smb = smem_u32(sm);
    const int nIter = K / PBK;

    auto issue_stage = [&](int stage, int k0) {
        #pragma unroll
        for (int i = 0; i < 4; ++i) {
            int idx = tid + i * 256;
            int buf = idx >> 9;
            int j   = idx & 511;
            int r   = j >> 2;
            int c16 = j & 3;
            int grow;
            if (buf == 0) {
                grow = irows[r];
            } else {
                int wr = bn + r;
                grow = (wr < N) ? wr : -1;
            }
            unsigned dst = smb + stage * STAGE_B + buf * TILE_B + r * 80 + c16 * 16;
            const char* src = (const char*)srcs[buf]
                            + ((size_t)(grow < 0 ? 0 : grow) * K + k0) * 2 + c16 * 16;
            cp16(dst, src, grow >= 0 ? 16 : 0);
        }
        asm volatile("cp.async.commit_group;" ::: "memory");
    };

    issue_stage(0, 0);
    issue_stage(1, PBK);

    for (int c = 0; c < nIter; ++c) {
        if (c < nIter - 1) {
            asm volatile("cp.async.wait_group 1;" ::: "memory");
        } else {
            asm volatile("cp.async.wait_group 0;" ::: "memory");
        }
        __syncthreads();

        if (c + 2 < nIter) {
            int nb = c + 2;
            int st = nb - (nb / NSTAGE) * NSTAGE;
            issue_stage(st, nb * PBK);
        }

        int cs = c - (c / NSTAGE) * NSTAGE;
        char* st = sm + cs * STAGE_B;
        __half (*sA)[PLD] = (__half (*)[PLD])(st);
        __half (*sW)[PLD] = (__half (*)[PLD])(st + TILE_B);

        #pragma unroll
        for (int ks = 0; ks < 2; ++ks) {
            const int kk = ks * 16;
            unsigned av[4][4], bv[4][2];
            const int lr = lane & 15;
            const int lk = (lane >> 4) * 8;
            #pragma unroll
            for (int mi = 0; mi < 4; ++mi) {
                ldsm_x4(av[mi], &sA[wm * 64 + mi * 16 + lr][kk + lk]);
            }
            const int l8  = lane & 7;
            const int lk2 = ((lane >> 3) & 1) * 8;
            #pragma unroll
            for (int ni = 0; ni < 4; ++ni) {
                ldsm_x2(bv[ni], &sW[wn * 32 + ni * 8 + l8][kk + lk2]);
            }
            #pragma unroll
            for (int mi = 0; mi < 4; ++mi) {
                #pragma unroll
                for (int ni = 0; ni < 4; ++ni) {
                    mma_h16(acc[mi][ni], av[mi], bv[ni]);
                }
            }
        }
    }

    #pragma unroll
    for (int mi = 0; mi < 4; ++mi) {
        int r0 = bm + wm * 64 + mi * 16 + (lane >> 2);
        #pragma unroll
        for (int ni = 0; ni < 4; ++ni) {
            int c = bn + wn * 32 + ni * 8 + (lane & 3) * 2;
            float b0 = bias[c];
            float b1 = bias[c + 1];
            float v0 = acc[mi][ni][0] + b0;
            float v1 = acc[mi][ni][1] + b1;
            float v2 = acc[mi][ni][2] + b0;
            float v3 = acc[mi][ni][3] + b1;
            if (relu) {
                v0 = fmaxf(v0, 0.f); v1 = fmaxf(v1, 0.f);
                v2 = fmaxf(v2, 0.f); v3 = fmaxf(v3, 0.f);
            }
            if (r0 < M) {
                size_t o = (size_t)r0 * N + c;
                if (Cf) *(float2*)(Cf + o) = make_float2(v0, v1);
                if (Ch) *(unsigned*)(Ch + o) = pack_h2(v0, v1);
            }
            if (r0 + 8 < M) {
                size_t o = (size_t)(r0 + 8) * N + c;
                if (Cf) *(float2*)(Cf + o) = make_float2(v2, v3);
                if (Ch) *(unsigned*)(Ch + o) = pack_h2(v2, v3);
            }
        }
    }
}

// ============================================================
// LayerNorm with residual; optional fp16 secondary output.
// ============================================================
__global__ void ln_res(const float* __restrict__ A, const float* __restrict__ R,
                       const int* __restrict__ rmap,
                       const float* __restrict__ g, const float* __restrict__ beta,
                       float* __restrict__ out, __half* __restrict__ outH)
{
    int row = blockIdx.x;
    int tid = threadIdx.x;   // 128
    __shared__ float red [128];
    __shared__ float red2[128];
    int rrow = rmap ? rmap[row] : row;
    float4 x = ((const float4*)(A + (size_t)row*DM))[tid];
    float4 r = ((const float4*)(R + (size_t)rrow*DM))[tid];
    x.x += r.x; x.y += r.y; x.z += r.z; x.w += r.w;
    red [tid] = x.x + x.y + x.z + x.w;
    red2[tid] = x.x*x.x + x.y*x.y + x.z*x.z + x.w*x.w;
    __syncthreads();
    #pragma unroll
    for (int o = 64; o > 0; o >>= 1) {
        if (tid < o) { red[tid] += red[tid+o]; red2[tid] += red2[tid+o]; }
        __syncthreads();
    }
    float mean = red[0] * (1.f/512.f);
    float var  = red2[0] * (1.f/512.f) - mean*mean;
    float inv  = rsqrtf(var + 1e-5f);
    float4 gg = ((const float4*)g)[tid];
    float4 bb = ((const float4*)beta)[tid];
    float4 o4;
    o4.x = (x.x - mean)*inv*gg.x + bb.x;
    o4.y = (x.y - mean)*inv*gg.y + bb.y;
    o4.z = (x.z - mean)*inv*gg.z + bb.z;
    o4.w = (x.w - mean)*inv*gg.w + bb.w;
    ((float4*)(out + (size_t)row*DM))[tid] = o4;
    if (outH) {
        size_t o = (size_t)row * DM + tid * 4;
        uint2 u;
        u.x = pack_h2(o4.x, o4.y);
        u.y = pack_h2(o4.z, o4.w);
        *(uint2*)(outH + o) = u;
    }
}

// ============================================================
// Tensor-core flash attention: GEMM-proven ldsm paths only.
// Q/K tiles are 64-dim rows -> 72-col padded layout (FIXED).
// Block = (64 queries, head, batch); 4 warps x 16 queries.
// ============================================================
#define NEG_BIAS (-30000.f)

__global__ __launch_bounds__(128, 2)
void attn_mma(const __half* __restrict__ Qh, const __half* __restrict__ Kh,
              const __half* __restrict__ Vh, const int* __restrict__ mask,
              __half* __restrict__ ctxH, int Lq, int Lv)
{
    __shared__ __half sQ [64][72];       // 64 queries x 64 dims (+8 pad)
    __shared__ __half sK [32][72];       // 32 keys x 64 dims (+8 pad)
    __shared__ __half sVt[64][40];       // transposed: [dim][key] (32 keys +8)
    __shared__ __half sB [64][36];
    __shared__ __half sP [4][16][40];    // per-warp P tile (32 keys +8)

    const int qt = blockIdx.x, h = blockIdx.y, b = blockIdx.z;
    const int tid = threadIdx.x, lane = tid & 31, wid = tid >> 5;
    const int g = lane >> 2, tg = lane & 3;

    // ---- stage Q tile (64 x 64 fp16) ----
    #pragma unroll
    for (int i = 0; i < 4; ++i) {
        int idx = tid + i * 128;
        int r = idx >> 3, c8 = idx & 7;
        int q = qt * 64 + r;
        uint4 v = make_uint4(0u, 0u, 0u, 0u);
        if (q < Lq) {
            v = *(const uint4*)(Qh + ((size_t)(b * Lq + q)) * DM + h * DKH + c8 * 8);
        }
        *(uint4*)&sQ[r][c8 * 8] = v;
    }
    __syncthreads();

    // per-warp Q fragments (16 queries x 64 dims, 4 k-chunks) — GEMM A-path
    unsigned qf[4][4];
    {
        int lr = lane & 15, lk = (lane >> 4) * 8;
        #pragma unroll
        for (int kc = 0; kc < 4; ++kc) {
            ldsm_x4(qf[kc], &sQ[wid * 16 + lr][kc * 16 + lk]);
        }
    }

    float o[8][4];
    #pragma unroll
    for (int dt = 0; dt < 8; ++dt) {
        #pragma unroll
        for (int j = 0; j < 4; ++j) o[dt][j] = 0.f;
    }
    float mr0 = -1e30f, mr1 = -1e30f, lr0 = 0.f, lr1 = 0.f;

    for (int kv0 = 0; kv0 < Lv; kv0 += 32) {
        __syncthreads();   // previous tile's compute fully done

        // ---- load K rows; load V rows and TRANSPOSE into sVt ----
        #pragma unroll
        for (int i = 0; i < 2; ++i) {
            int idx = tid + i * 128;      // 0..255
            int r = idx >> 3, c8 = idx & 7;
            int kv = kv0 + r;
            uint4 kvv = make_uint4(0u, 0u, 0u, 0u);
            uint4 vvv = make_uint4(0u, 0u, 0u, 0u);
            if (kv < Lv) {
                size_t base = ((size_t)(b * Lv + kv)) * DM + h * DKH + c8 * 8;
                kvv = *(const uint4*)(Kh + base);
                vvv = *(const uint4*)(Vh + base);
            }
            *(uint4*)&sK[r][c8 * 8] = kvv;
            const __half* vh8 = (const __half*)&vvv;
            #pragma unroll
            for (int j = 0; j < 8; ++j) {
                sVt[c8 * 8 + j][r] = vh8[j];
            }
        }
        // ---- mask -> fp16 bias tile (64q x 32k); scalar loads ----
        #pragma unroll
        for (int i = 0; i < 4; ++i) {
            int idx = tid + i * 128;
            int r = idx >> 3, c4 = (idx & 7) * 4;
            int q = qt * 64 + r;
            float f[4];
            if (q < Lq) {
                const int* mrow = mask + ((size_t)(b * Lq + q)) * Lv;
                #pragma unroll
                for (int j = 0; j < 4; ++j) {
                    int kv = kv0 + c4 + j;
                    int m = (kv < Lv) ? __ldg(mrow + kv) : 1;
                    f[j] = m ? NEG_BIAS : 0.f;
                }
            } else {
                f[0] = f[1] = f[2] = f[3] = NEG_BIAS;
            }
            uint2 u;
            u.x = pack_h2(f[0], f[1]);
            u.y = pack_h2(f[2], f[3]);
            *(uint2*)&sB[r][c4] = u;
        }
        __syncthreads();

        // ---- QK^T (GEMM-proven paths) ----
        float sc[4][4];
        #pragma unroll
        for (int nt = 0; nt < 4; ++nt) {
            #pragma unroll
            for (int j = 0; j < 4; ++j) sc[nt][j] = 0.f;
        }
        {
            int l8 = lane & 7, lk2 = ((lane >> 3) & 1) * 8;
            #pragma unroll
            for (int nt = 0; nt < 4; ++nt) {
                #pragma unroll
                for (int kc = 0; kc < 4; ++kc) {
                    unsigned bf[2];
                    ldsm_x2(bf, &sK[nt * 8 + l8][kc * 16 + lk2]);
                    mma_h16(sc[nt], qf[kc], bf);
                }
            }
        }

        // ---- scale + bias + online softmax ----
        float tm0 = -1e30f, tm1 = -1e30f;
        #pragma unroll
        for (int nt = 0; nt < 4; ++nt) {
            __half2 hb0 = *(__half2*)&sB[wid * 16 + g][nt * 8 + tg * 2];
            __half2 hb1 = *(__half2*)&sB[wid * 16 + g + 8][nt * 8 + tg * 2];
            float2 b0 = __half22float2(hb0);
            float2 b1 = __half22float2(hb1);
            sc[nt][0] = sc[nt][0] * 0.125f + b0.x;
            sc[nt][1] = sc[nt][1] * 0.125f + b0.y;
            sc[nt][2] = sc[nt][2] * 0.125f + b1.x;
            sc[nt][3] = sc[nt][3] * 0.125f + b1.y;
            tm0 = fmaxf(tm0, fmaxf(sc[nt][0], sc[nt][1]));
            tm1 = fmaxf(tm1, fmaxf(sc[nt][2], sc[nt][3]));
        }
        tm0 = fmaxf(tm0, __shfl_xor_sync(0xffffffffu, tm0, 1));
        tm0 = fmaxf(tm0, __shfl_xor_sync(0xffffffffu, tm0, 2));
        tm1 = fmaxf(tm1, __shfl_xor_sync(0xffffffffu, tm1, 1));
        tm1 = fmaxf(tm1, __shfl_xor_sync(0xffffffffu, tm1, 2));

        float mn0 = fmaxf(mr0, tm0);
        float mn1 = fmaxf(mr1, tm1);
        float s0 = __expf(mr0 - mn0);
        float s1 = __expf(mr1 - mn1);

        float ts0 = 0.f, ts1 = 0.f;
        #pragma unroll
        for (int nt = 0; nt < 4; ++nt) {
            sc[nt][0] = __expf(sc[nt][0] - mn0);
            sc[nt][1] = __expf(sc[nt][1] - mn0);
            sc[nt][2] = __expf(sc[nt][2] - mn1);
            sc[nt][3] = __expf(sc[nt][3] - mn1);
            ts0 += sc[nt][0] + sc[nt][1];
            ts1 += sc[nt][2] + sc[nt][3];
        }
        ts0 += __shfl_xor_sync(0xffffffffu, ts0, 1);
        ts0 += __shfl_xor_sync(0xffffffffu, ts0, 2);
        ts1 += __shfl_xor_sync(0xffffffffu, ts1, 1);
        ts1 += __shfl_xor_sync(0xffffffffu, ts1, 2);

        lr0 = lr0 * s0 + ts0;
        lr1 = lr1 * s1 + ts1;
        mr0 = mn0;
        mr1 = mn1;
        #pragma unroll
        for (int dt = 0; dt < 8; ++dt) {
            o[dt][0] *= s0; o[dt][1] *= s0;
            o[dt][2] *= s1; o[dt][3] *= s1;
        }

        // ---- write P to per-warp smem (C-layout half2 stores) ----
        #pragma unroll
        for (int nt = 0; nt < 4; ++nt) {
            *(unsigned*)&sP[wid][g][nt * 8 + tg * 2]     = pack_h2(sc[nt][0], sc[nt][1]);
            *(unsigned*)&sP[wid][g + 8][nt * 8 + tg * 2] = pack_h2(sc[nt][2], sc[nt][3]);
        }
        __syncwarp();

        // ---- PV: A = P via GEMM A-path, B = sVt via GEMM W-path ----
        {
            int lr = lane & 15, lk = (lane >> 4) * 8;
            int l8 = lane & 7, lk2 = ((lane >> 3) & 1) * 8;
            #pragma unroll
            for (int kc2 = 0; kc2 < 2; ++kc2) {
                unsigned pA[4];
                ldsm_x4(pA, &sP[wid][lr][kc2 * 16 + lk]);
                #pragma unroll
                for (int ni = 0; ni < 8; ++ni) {
                    unsigned bf[2];
                    ldsm_x2(bf, &sVt[ni * 8 + l8][kc2 * 16 + lk2]);
                    mma_h16(o[ni], pA, bf);
                }
            }
        }
        __syncwarp();
    }

    // ---- write output (fp16 ctx) ----
    float inv0 = 1.f / lr0;
    float inv1 = 1.f / lr1;
    int q0 = qt * 64 + wid * 16 + g;
    int q1 = q0 + 8;
    #pragma unroll
    for (int dt = 0; dt < 8; ++dt) {
        int col = h * DKH + dt * 8 + tg * 2;
        if (q0 < Lq) {
            *(unsigned*)(ctxH + ((size_t)(b * Lq + q0)) * DM + col)
                = pack_h2(o[dt][0] * inv0, o[dt][1] * inv0);
        }
        if (q1 < Lq) {
            *(unsigned*)(ctxH + ((size_t)(b * Lq + q1)) * DM + col)
                = pack_h2(o[dt][2] * inv1, o[dt][3] * inv1);
        }
    }
}

// ============================================================
// launcher
// ============================================================
extern "C" void kernel_launch(void* const* d_in, const int* in_sizes, int n_in,
                              void* d_out, int out_size)
{
    const float* ent   = (const float*)d_in[0];
    const float* pred  = (const float*)d_in[1];
    const float* w_qs  = (const float*)d_in[2];
    const float* b_qs  = (const float*)d_in[3];
    const float* w_ks  = (const float*)d_in[4];
    const float* b_ks  = (const float*)d_in[5];
    const float* w_vs  = (const float*)d_in[6];
    const float* b_vs  = (const float*)d_in[7];
    const float* w_fc  = (const float*)d_in[8];
    const float* b_fc  = (const float*)d_in[9];
    const float* ln1_g = (const float*)d_in[10];
    const float* ln1_b = (const float*)d_in[11];
    const float* w1    = (const float*)d_in[12];
    const float* b1    = (const float*)d_in[13];
    const float* w2    = (const float*)d_in[14];
    const float* b2    = (const float*)d_in[15];
    const float* ln2_g = (const float*)d_in[16];
    const float* ln2_b = (const float*)d_in[17];
    const int*   amask = (const int*)d_in[18];
    const int*   gidx  = (const int*)d_in[20];

    int Lq  = in_sizes[0] / (BSZ * DM);
    int Lv  = in_sizes[1] / (BSZ * DM);
    int nv  = in_sizes[20];
    int MKV = BSZ * Lv;
    int MQ  = BSZ * Lq;

    float *pT0, *pX;
    cudaGetSymbolAddress((void**)&pT0, g_t0);
    cudaGetSymbolAddress((void**)&pX,  g_x);

    __half *predh, *enth, *qh, *kh, *vh, *ctxh, *xh, *hh;
    __half *wqh, *wkh, *wvh, *wfh, *w1h, *w2h;
    cudaGetSymbolAddress((void**)&predh, g_predh);
    cudaGetSymbolAddress((void**)&enth,  g_enth);
    cudaGetSymbolAddress((void**)&qh,    g_qh);
    cudaGetSymbolAddress((void**)&kh,    g_kh);
    cudaGetSymbolAddress((void**)&vh,    g_vh);
    cudaGetSymbolAddress((void**)&ctxh,  g_ctxh);
    cudaGetSymbolAddress((void**)&xh,    g_xh);
    cudaGetSymbolAddress((void**)&hh,    g_hh);
    cudaGetSymbolAddress((void**)&wqh,   g_wqh);
    cudaGetSymbolAddress((void**)&wkh,   g_wkh);
    cudaGetSymbolAddress((void**)&wvh,   g_wvh);
    cudaGetSymbolAddress((void**)&wfh,   g_wfh);
    cudaGetSymbolAddress((void**)&w1h,   g_w1h);
    cudaGetSymbolAddress((void**)&w2h,   g_w2h);

    cudaFuncSetAttribute(gemm_h, cudaFuncAttributeMaxDynamicSharedMemorySize, GEMM_SMEM);

    // ---- launch 0: all conversions fused ----
    {
        CvtArgs a;
        const float* s[8] = {pred, ent, w_qs, w_ks, w_vs, w_fc, w1, w2};
        __half*      d[8] = {predh, enth, wqh, wkh, wvh, wfh, w1h, w2h};
        int len4[8] = {MKV*DM/4, MQ*DM/4, DM*DM/4, DM*DM/4, DM*DM/4, DM*DM/4,
                       DI*DM/4, DM*DI/4};
        int acc = 0;
        for (int i = 0; i < 8; ++i) {
            a.src[i] = (const float4*)s[i];
            a.dst[i] = (uint2*)d[i];
            a.off[i] = acc;
            acc += len4[i];
        }
        a.off[8] = acc;
        cvt_all<<<(acc + 255) / 256, 256>>>(a);
    }

    // launches 1-3: Q, K, V projections (emit fp16 only)
    {
        dim3 grd(DM / PBN, (MQ + PBM - 1) / PBM);
        gemm_h<<<grd, 256, GEMM_SMEM>>>(enth, nullptr, wqh, b_qs,
                                        nullptr, qh, MQ, DM, DM, 0);
    }
    {
        dim3 grd(DM / PBN, (MKV + PBM - 1) / PBM);
        gemm_h<<<grd, 256, GEMM_SMEM>>>(predh, nullptr, wkh, b_ks,
                                        nullptr, kh, MKV, DM, DM, 0);
        gemm_h<<<grd, 256, GEMM_SMEM>>>(predh, nullptr, wvh, b_vs,
                                        nullptr, vh, MKV, DM, DM, 0);
    }
    // launch 4: tensor-core attention
    {
        dim3 grd((Lq + 63) / 64, NH, BSZ);
        attn_mma<<<grd, 128>>>(qh, kh, vh, amask, ctxh, Lq, Lv);
    }
    // launch 5: fc gemm (gathers valid rows); 6: ln1
    {
        dim3 grd(DM / PBN, (nv + PBM - 1) / PBM);
        gemm_h<<<grd, 256, GEMM_SMEM>>>(ctxh, gidx, wfh, b_fc,
                                        pT0, nullptr, nv, DM, DM, 0);
        ln_res<<<nv, 128>>>(pT0, ent, gidx, ln1_g, ln1_b, pX, xh);
    }
    // launches 7-9: FFN + ln2
    {
        dim3 grd(DI / PBN, (nv + PBM - 1) / PBM);
        gemm_h<<<grd, 256, GEMM_SMEM>>>(xh, nullptr, w1h, b1,
                                        nullptr, hh, nv, DI, DM, 1);
    }
    {
        dim3 grd(DM / PBN, (nv + PBM - 1) / PBM);
        gemm_h<<<grd, 256, GEMM_SMEM>>>(hh, nullptr, w2h, b2,
                                        pT0, nullptr, nv, DM, DI, 0);
        ln_res<<<nv, 128>>>(pT0, pX, nullptr, ln2_g, ln2_b, (float*)d_out, nullptr);
    }
}

// round 16
// speedup vs baseline: 5.6423x; 1.0658x over previous
#include <cuda_runtime.h>
#include <cuda_fp16.h>
#include <cstdint>
#include <math.h>

#define DM 512
#define DI 2048
#define NH 8
#define DKH 64
#define BSZ 32
#define MAXROWS (32*160)
#define MAXKV   (32*640)

// ---- fp32 scratch ----
__device__ float g_t0 [MAXROWS*DM];
__device__ float g_t1 [MAXROWS*DM];
__device__ float g_x  [MAXROWS*DM];

// ---- fp16 scratch ----
__device__ __align__(16) __half g_predh[MAXKV*DM];
__device__ __align__(16) __half g_enth [MAXROWS*DM];
__device__ __align__(16) __half g_qh   [MAXROWS*DM];
__device__ __align__(16) __half g_kh   [MAXKV*DM];
__device__ __align__(16) __half g_vh   [MAXKV*DM];
__device__ __align__(16) __half g_ctxh [MAXROWS*DM];
__device__ __align__(16) __half g_xh   [MAXROWS*DM];
__device__ __align__(16) __half g_hh   [MAXROWS*DI];
__device__ __align__(16) __half g_wqh[DM*DM];
__device__ __align__(16) __half g_wkh[DM*DM];
__device__ __align__(16) __half g_wvh[DM*DM];
__device__ __align__(16) __half g_wfh[DM*DM];
__device__ __align__(16) __half g_w1h[DI*DM];
__device__ __align__(16) __half g_w2h[DM*DI];

__device__ __forceinline__ unsigned pack_h2(float a, float b) {
    __half2 t = __floats2half2_rn(a, b);
    return *(unsigned*)&t;
}

// ============================================================
// Fused fp32 -> fp16 conversion over 8 segments, ONE launch.
// ============================================================
struct CvtArgs {
    const float4* src[8];
    uint2*        dst[8];
    int           off[9];
};

__global__ void cvt_all(CvtArgs a)
{
    int i = blockIdx.x * blockDim.x + threadIdx.x;
    if (i >= a.off[8]) return;
    int s = 0;
    #pragma unroll
    for (int k = 1; k < 8; ++k) {
        if (i >= a.off[k]) s = k;
    }
    int local = i - a.off[s];
    float4 v = a.src[s][local];
    uint2 u;
    u.x = pack_h2(v.x, v.y);
    u.y = pack_h2(v.z, v.w);
    a.dst[s][local] = u;
}

// ============================================================
// shared helpers
// ============================================================
__device__ __forceinline__ unsigned smem_u32(const void* p) {
    return (unsigned)__cvta_generic_to_shared(p);
}
__device__ __forceinline__ void cp16(unsigned dst, const void* src, int sz) {
    asm volatile("cp.async.cg.shared.global [%0], [%1], 16, %2;"
        :: "r"(dst), "l"(src), "r"(sz) : "memory");
}
__device__ __forceinline__ void ldsm_x4(unsigned* r, const void* p) {
    unsigned a = smem_u32(p);
    asm volatile("ldmatrix.sync.aligned.m8n8.x4.shared.b16 {%0,%1,%2,%3}, [%4];"
        : "=r"(r[0]), "=r"(r[1]), "=r"(r[2]), "=r"(r[3]) : "r"(a));
}
__device__ __forceinline__ void ldsm_x2(unsigned* r, const void* p) {
    unsigned a = smem_u32(p);
    asm volatile("ldmatrix.sync.aligned.m8n8.x2.shared.b16 {%0,%1}, [%2];"
        : "=r"(r[0]), "=r"(r[1]) : "r"(a));
}
__device__ __forceinline__ void mma_h16(float* c, const unsigned* a, const unsigned* b) {
    asm volatile("mma.sync.aligned.m16n8k16.row.col.f32.f16.f16.f32 "
        "{%0,%1,%2,%3}, {%4,%5,%6,%7}, {%8,%9}, {%0,%1,%2,%3};"
        : "+f"(c[0]), "+f"(c[1]), "+f"(c[2]), "+f"(c[3])
        : "r"(a[0]), "r"(a[1]), "r"(a[2]), "r"(a[3]), "r"(b[0]), "r"(b[1]));
}

// ============================================================
// 2-stage pipelined fp16 mma.sync GEMM, BK=64, split-K capable.
// C[M,N] = A[M, k0:k0+Ksub] @ W[N, k0:k0+Ksub]^T (+ bias).
// 128x128 tile, 256 thr, warp tile 64x32, rows padded to 144B.
// ============================================================
#define PBM 128
#define PBN 128
#define PBK 64
#define PLD 72
#define TILE_B (PBM*PLD*2)        // 18432 B per tile
#define STAGE_B (2*TILE_B)        // 36864 B per stage
#define GEMM_SMEM (2*STAGE_B)     // 73728 B dynamic

__global__ __launch_bounds__(256, 2)
void gemm_h(const __half* __restrict__ A, const int* __restrict__ rmap,
            const __half* __restrict__ W, const float* __restrict__ bias,
            float* __restrict__ Cf, __half* __restrict__ Ch,
            int M, int N, int Ksub, int lda, int k0, int relu)
{
    extern __shared__ char sm[];
    __shared__ int irows[PBM];

    const int tid  = threadIdx.x;
    const int lane = tid & 31;
    const int wid  = tid >> 5;
    const int wm   = wid >> 2;
    const int wn   = wid & 3;
    const int bm = blockIdx.y * PBM;
    const int bn = blockIdx.x * PBN;

    if (tid < PBM) {
        int ar = bm + tid;
        irows[tid] = (ar < M) ? (rmap ? rmap[ar] : ar) : -1;
    }
    __syncthreads();

    const __half* srcs[2] = {A, W};

    float acc[4][4][4];
    #pragma unroll
    for (int mi = 0; mi < 4; ++mi) {
        #pragma unroll
        for (int ni = 0; ni < 4; ++ni) {
            #pragma unroll
            for (int j = 0; j < 4; ++j) acc[mi][ni][j] = 0.f;
        }
    }

    const unsigned smb = smem_u32(sm);
    const int nIter = Ksub / PBK;

    // issue one 64-wide k-block: 8 x 16B chunks per thread (2048 total)
    auto issue_stage = [&](int stage, int kblk) {
        #pragma unroll
        for (int i = 0; i < 8; ++i) {
            int idx = tid + i * 256;      // 0..2047
            int buf = idx >> 10;          // 0=A, 1=W
            int j   = idx & 1023;
            int r   = j >> 3;
            int c16 = j & 7;
            int grow;
            if (buf == 0) {
                grow = irows[r];
            } else {
                int wr = bn + r;
                grow = (wr < N) ? wr : -1;
            }
            unsigned dst = smb + stage * STAGE_B + buf * TILE_B + r * 144 + c16 * 16;
            const char* src = (const char*)srcs[buf]
                            + ((size_t)(grow < 0 ? 0 : grow) * lda + k0 + kblk) * 2 + c16 * 16;
            cp16(dst, src, grow >= 0 ? 16 : 0);
        }
        asm volatile("cp.async.commit_group;" ::: "memory");
    };

    issue_stage(0, 0);

    for (int c = 0; c < nIter; ++c) {
        if (c + 1 < nIter) {
            issue_stage((c + 1) & 1, (c + 1) * PBK);
            asm volatile("cp.async.wait_group 1;" ::: "memory");
        } else {
            asm volatile("cp.async.wait_group 0;" ::: "memory");
        }
        __syncthreads();

        char* st = sm + (c & 1) * STAGE_B;
        __half (*sA)[PLD] = (__half (*)[PLD])(st);
        __half (*sW)[PLD] = (__half (*)[PLD])(st + TILE_B);

        #pragma unroll
        for (int ks = 0; ks < 4; ++ks) {
            const int kk = ks * 16;
            unsigned av[4][4], bv[4][2];
            const int lr = lane & 15;
            const int lk = (lane >> 4) * 8;
            #pragma unroll
            for (int mi = 0; mi < 4; ++mi) {
                ldsm_x4(av[mi], &sA[wm * 64 + mi * 16 + lr][kk + lk]);
            }
            const int l8  = lane & 7;
            const int lk2 = ((lane >> 3) & 1) * 8;
            #pragma unroll
            for (int ni = 0; ni < 4; ++ni) {
                ldsm_x2(bv[ni], &sW[wn * 32 + ni * 8 + l8][kk + lk2]);
            }
            #pragma unroll
            for (int mi = 0; mi < 4; ++mi) {
                #pragma unroll
                for (int ni = 0; ni < 4; ++ni) {
                    mma_h16(acc[mi][ni], av[mi], bv[ni]);
                }
            }
        }
        __syncthreads();
    }

    #pragma unroll
    for (int mi = 0; mi < 4; ++mi) {
        int r0 = bm + wm * 64 + mi * 16 + (lane >> 2);
        #pragma unroll
        for (int ni = 0; ni < 4; ++ni) {
            int c = bn + wn * 32 + ni * 8 + (lane & 3) * 2;
            float b0 = bias ? bias[c]     : 0.f;
            float b1 = bias ? bias[c + 1] : 0.f;
            float v0 = acc[mi][ni][0] + b0;
            float v1 = acc[mi][ni][1] + b1;
            float v2 = acc[mi][ni][2] + b0;
            float v3 = acc[mi][ni][3] + b1;
            if (relu) {
                v0 = fmaxf(v0, 0.f); v1 = fmaxf(v1, 0.f);
                v2 = fmaxf(v2, 0.f); v3 = fmaxf(v3, 0.f);
            }
            if (r0 < M) {
                size_t o = (size_t)r0 * N + c;
                if (Cf) *(float2*)(Cf + o) = make_float2(v0, v1);
                if (Ch) *(unsigned*)(Ch + o) = pack_h2(v0, v1);
            }
            if (r0 + 8 < M) {
                size_t o = (size_t)(r0 + 8) * N + c;
                if (Cf) *(float2*)(Cf + o) = make_float2(v2, v3);
                if (Ch) *(unsigned*)(Ch + o) = pack_h2(v2, v3);
            }
        }
    }
}

// ============================================================
// LayerNorm with residual: out = LN(A (+A1) + R); optional fp16 out.
// ============================================================
__global__ void ln_res(const float* __restrict__ A, const float* __restrict__ A1,
                       const float* __restrict__ R, const int* __restrict__ rmap,
                       const float* __restrict__ g, const float* __restrict__ beta,
                       float* __restrict__ out, __half* __restrict__ outH)
{
    int row = blockIdx.x;
    int tid = threadIdx.x;   // 128
    __shared__ float red [128];
    __shared__ float red2[128];
    int rrow = rmap ? rmap[row] : row;
    float4 x = ((const float4*)(A + (size_t)row*DM))[tid];
    float4 r = ((const float4*)(R + (size_t)rrow*DM))[tid];
    x.x += r.x; x.y += r.y; x.z += r.z; x.w += r.w;
    if (A1) {
        float4 y = ((const float4*)(A1 + (size_t)row*DM))[tid];
        x.x += y.x; x.y += y.y; x.z += y.z; x.w += y.w;
    }
    red [tid] = x.x + x.y + x.z + x.w;
    red2[tid] = x.x*x.x + x.y*x.y + x.z*x.z + x.w*x.w;
    __syncthreads();
    #pragma unroll
    for (int o = 64; o > 0; o >>= 1) {
        if (tid < o) { red[tid] += red[tid+o]; red2[tid] += red2[tid+o]; }
        __syncthreads();
    }
    float mean = red[0] * (1.f/512.f);
    float var  = red2[0] * (1.f/512.f) - mean*mean;
    float inv  = rsqrtf(var + 1e-5f);
    float4 gg = ((const float4*)g)[tid];
    float4 bb = ((const float4*)beta)[tid];
    float4 o4;
    o4.x = (x.x - mean)*inv*gg.x + bb.x;
    o4.y = (x.y - mean)*inv*gg.y + bb.y;
    o4.z = (x.z - mean)*inv*gg.z + bb.z;
    o4.w = (x.w - mean)*inv*gg.w + bb.w;
    ((float4*)(out + (size_t)row*DM))[tid] = o4;
    if (outH) {
        size_t o = (size_t)row * DM + tid * 4;
        uint2 u;
        u.x = pack_h2(o4.x, o4.y);
        u.y = pack_h2(o4.z, o4.w);
        *(uint2*)(outH + o) = u;
    }
}

// ============================================================
// Tensor-core flash attention (passing, R15). Unchanged.
// ============================================================
#define NEG_BIAS (-30000.f)

__global__ __launch_bounds__(128, 2)
void attn_mma(const __half* __restrict__ Qh, const __half* __restrict__ Kh,
              const __half* __restrict__ Vh, const int* __restrict__ mask,
              __half* __restrict__ ctxH, int Lq, int Lv)
{
    __shared__ __half sQ [64][72];
    __shared__ __half sK [32][72];
    __shared__ __half sVt[64][40];
    __shared__ __half sB [64][36];
    __shared__ __half sP [4][16][40];

    const int qt = blockIdx.x, h = blockIdx.y, b = blockIdx.z;
    const int tid = threadIdx.x, lane = tid & 31, wid = tid >> 5;
    const int g = lane >> 2, tg = lane & 3;

    #pragma unroll
    for (int i = 0; i < 4; ++i) {
        int idx = tid + i * 128;
        int r = idx >> 3, c8 = idx & 7;
        int q = qt * 64 + r;
        uint4 v = make_uint4(0u, 0u, 0u, 0u);
        if (q < Lq) {
            v = *(const uint4*)(Qh + ((size_t)(b * Lq + q)) * DM + h * DKH + c8 * 8);
        }
        *(uint4*)&sQ[r][c8 * 8] = v;
    }
    __syncthreads();

    unsigned qf[4][4];
    {
        int lr = lane & 15, lk = (lane >> 4) * 8;
        #pragma unroll
        for (int kc = 0; kc < 4; ++kc) {
            ldsm_x4(qf[kc], &sQ[wid * 16 + lr][kc * 16 + lk]);
        }
    }

    float o[8][4];
    #pragma unroll
    for (int dt = 0; dt < 8; ++dt) {
        #pragma unroll
        for (int j = 0; j < 4; ++j) o[dt][j] = 0.f;
    }
    float mr0 = -1e30f, mr1 = -1e30f, lr0 = 0.f, lr1 = 0.f;

    for (int kv0 = 0; kv0 < Lv; kv0 += 32) {
        __syncthreads();

        #pragma unroll
        for (int i = 0; i < 2; ++i) {
            int idx = tid + i * 128;
            int r = idx >> 3, c8 = idx & 7;
            int kv = kv0 + r;
            uint4 kvv = make_uint4(0u, 0u, 0u, 0u);
            uint4 vvv = make_uint4(0u, 0u, 0u, 0u);
            if (kv < Lv) {
                size_t base = ((size_t)(b * Lv + kv)) * DM + h * DKH + c8 * 8;
                kvv = *(const uint4*)(Kh + base);
                vvv = *(const uint4*)(Vh + base);
            }
            *(uint4*)&sK[r][c8 * 8] = kvv;
            const __half* vh8 = (const __half*)&vvv;
            #pragma unroll
            for (int j = 0; j < 8; ++j) {
                sVt[c8 * 8 + j][r] = vh8[j];
            }
        }
        #pragma unroll
        for (int i = 0; i < 4; ++i) {
            int idx = tid + i * 128;
            int r = idx >> 3, c4 = (idx & 7) * 4;
            int q = qt * 64 + r;
            float f[4];
            if (q < Lq) {
                const int* mrow = mask + ((size_t)(b * Lq + q)) * Lv;
                #pragma unroll
                for (int j = 0; j < 4; ++j) {
                    int kv = kv0 + c4 + j;
                    int m = (kv < Lv) ? __ldg(mrow + kv) : 1;
                    f[j] = m ? NEG_BIAS : 0.f;
                }
            } else {
                f[0] = f[1] = f[2] = f[3] = NEG_BIAS;
            }
            uint2 u;
            u.x = pack_h2(f[0], f[1]);
            u.y = pack_h2(f[2], f[3]);
            *(uint2*)&sB[r][c4] = u;
        }
        __syncthreads();

        float sc[4][4];
        #pragma unroll
        for (int nt = 0; nt < 4; ++nt) {
            #pragma unroll
            for (int j = 0; j < 4; ++j) sc[nt][j] = 0.f;
        }
        {
            int l8 = lane & 7, lk2 = ((lane >> 3) & 1) * 8;
            #pragma unroll
            for (int nt = 0; nt < 4; ++nt) {
                #pragma unroll
                for (int kc = 0; kc < 4; ++kc) {
                    unsigned bf[2];
                    ldsm_x2(bf, &sK[nt * 8 + l8][kc * 16 + lk2]);
                    mma_h16(sc[nt], qf[kc], bf);
                }
            }
        }

        float tm0 = -1e30f, tm1 = -1e30f;
        #pragma unroll
        for (int nt = 0; nt < 4; ++nt) {
            __half2 hb0 = *(__half2*)&sB[wid * 16 + g][nt * 8 + tg * 2];
            __half2 hb1 = *(__half2*)&sB[wid * 16 + g + 8][nt * 8 + tg * 2];
            float2 b0 = __half22float2(hb0);
            float2 b1 = __half22float2(hb1);
            sc[nt][0] = sc[nt][0] * 0.125f + b0.x;
            sc[nt][1] = sc[nt][1] * 0.125f + b0.y;
            sc[nt][2] = sc[nt][2] * 0.125f + b1.x;
            sc[nt][3] = sc[nt][3] * 0.125f + b1.y;
            tm0 = fmaxf(tm0, fmaxf(sc[nt][0], sc[nt][1]));
            tm1 = fmaxf(tm1, fmaxf(sc[nt][2], sc[nt][3]));
        }
        tm0 = fmaxf(tm0, __shfl_xor_sync(0xffffffffu, tm0, 1));
        tm0 = fmaxf(tm0, __shfl_xor_sync(0xffffffffu, tm0, 2));
        tm1 = fmaxf(tm1, __shfl_xor_sync(0xffffffffu, tm1, 1));
        tm1 = fmaxf(tm1, __shfl_xor_sync(0xffffffffu, tm1, 2));

        float mn0 = fmaxf(mr0, tm0);
        float mn1 = fmaxf(mr1, tm1);
        float s0 = __expf(mr0 - mn0);
        float s1 = __expf(mr1 - mn1);

        float ts0 = 0.f, ts1 = 0.f;
        #pragma unroll
        for (int nt = 0; nt < 4; ++nt) {
            sc[nt][0] = __expf(sc[nt][0] - mn0);
            sc[nt][1] = __expf(sc[nt][1] - mn0);
            sc[nt][2] = __expf(sc[nt][2] - mn1);
            sc[nt][3] = __expf(sc[nt][3] - mn1);
            ts0 += sc[nt][0] + sc[nt][1];
            ts1 += sc[nt][2] + sc[nt][3];
        }
        ts0 += __shfl_xor_sync(0xffffffffu, ts0, 1);
        ts0 += __shfl_xor_sync(0xffffffffu, ts0, 2);
        ts1 += __shfl_xor_sync(0xffffffffu, ts1, 1);
        ts1 += __shfl_xor_sync(0xffffffffu, ts1, 2);

        lr0 = lr0 * s0 + ts0;
        lr1 = lr1 * s1 + ts1;
        mr0 = mn0;
        mr1 = mn1;
        #pragma unroll
        for (int dt = 0; dt < 8; ++dt) {
            o[dt][0] *= s0; o[dt][1] *= s0;
            o[dt][2] *= s1; o[dt][3] *= s1;
        }

        #pragma unroll
        for (int nt = 0; nt < 4; ++nt) {
            *(unsigned*)&sP[wid][g][nt * 8 + tg * 2]     = pack_h2(sc[nt][0], sc[nt][1]);
            *(unsigned*)&sP[wid][g + 8][nt * 8 + tg * 2] = pack_h2(sc[nt][2], sc[nt][3]);
        }
        __syncwarp();

        {
            int lr = lane & 15, lk = (lane >> 4) * 8;
            int l8 = lane & 7, lk2 = ((lane >> 3) & 1) * 8;
            #pragma unroll
            for (int kc2 = 0; kc2 < 2; ++kc2) {
                unsigned pA[4];
                ldsm_x4(pA, &sP[wid][lr][kc2 * 16 + lk]);
                #pragma unroll
                for (int ni = 0; ni < 8; ++ni) {
                    unsigned bf[2];
                    ldsm_x2(bf, &sVt[ni * 8 + l8][kc2 * 16 + lk2]);
                    mma_h16(o[ni], pA, bf);
                }
            }
        }
        __syncwarp();
    }

    float inv0 = 1.f / lr0;
    float inv1 = 1.f / lr1;
    int q0 = qt * 64 + wid * 16 + g;
    int q1 = q0 + 8;
    #pragma unroll
    for (int dt = 0; dt < 8; ++dt) {
        int col = h * DKH + dt * 8 + tg * 2;
        if (q0 < Lq) {
            *(unsigned*)(ctxH + ((size_t)(b * Lq + q0)) * DM + col)
                = pack_h2(o[dt][0] * inv0, o[dt][1] * inv0);
        }
        if (q1 < Lq) {
            *(unsigned*)(ctxH + ((size_t)(b * Lq + q1)) * DM + col)
                = pack_h2(o[dt][2] * inv1, o[dt][3] * inv1);
        }
    }
}

// ============================================================
// launcher
// ============================================================
extern "C" void kernel_launch(void* const* d_in, const int* in_sizes, int n_in,
                              void* d_out, int out_size)
{
    const float* ent   = (const float*)d_in[0];
    const float* pred  = (const float*)d_in[1];
    const float* w_qs  = (const float*)d_in[2];
    const float* b_qs  = (const float*)d_in[3];
    const float* w_ks  = (const float*)d_in[4];
    const float* b_ks  = (const float*)d_in[5];
    const float* w_vs  = (const float*)d_in[6];
    const float* b_vs  = (const float*)d_in[7];
    const float* w_fc  = (const float*)d_in[8];
    const float* b_fc  = (const float*)d_in[9];
    const float* ln1_g = (const float*)d_in[10];
    const float* ln1_b = (const float*)d_in[11];
    const float* w1    = (const float*)d_in[12];
    const float* b1    = (const float*)d_in[13];
    const float* w2    = (const float*)d_in[14];
    const float* b2    = (const float*)d_in[15];
    const float* ln2_g = (const float*)d_in[16];
    const float* ln2_b = (const float*)d_in[17];
    const int*   amask = (const int*)d_in[18];
    const int*   gidx  = (const int*)d_in[20];

    int Lq  = in_sizes[0] / (BSZ * DM);
    int Lv  = in_sizes[1] / (BSZ * DM);
    int nv  = in_sizes[20];
    int MKV = BSZ * Lv;
    int MQ  = BSZ * Lq;

    float *pT0, *pT1, *pX;
    cudaGetSymbolAddress((void**)&pT0, g_t0);
    cudaGetSymbolAddress((void**)&pT1, g_t1);
    cudaGetSymbolAddress((void**)&pX,  g_x);

    __half *predh, *enth, *qh, *kh, *vh, *ctxh, *xh, *hh;
    __half *wqh, *wkh, *wvh, *wfh, *w1h, *w2h;
    cudaGetSymbolAddress((void**)&predh, g_predh);
    cudaGetSymbolAddress((void**)&enth,  g_enth);
    cudaGetSymbolAddress((void**)&qh,    g_qh);
    cudaGetSymbolAddress((void**)&kh,    g_kh);
    cudaGetSymbolAddress((void**)&vh,    g_vh);
    cudaGetSymbolAddress((void**)&ctxh,  g_ctxh);
    cudaGetSymbolAddress((void**)&xh,    g_xh);
    cudaGetSymbolAddress((void**)&hh,    g_hh);
    cudaGetSymbolAddress((void**)&wqh,   g_wqh);
    cudaGetSymbolAddress((void**)&wkh,   g_wkh);
    cudaGetSymbolAddress((void**)&wvh,   g_wvh);
    cudaGetSymbolAddress((void**)&wfh,   g_wfh);
    cudaGetSymbolAddress((void**)&w1h,   g_w1h);
    cudaGetSymbolAddress((void**)&w2h,   g_w2h);

    cudaFuncSetAttribute(gemm_h, cudaFuncAttributeMaxDynamicSharedMemorySize, GEMM_SMEM);

    // ---- launch 0: all conversions fused ----
    {
        CvtArgs a;
        const float* s[8] = {pred, ent, w_qs, w_ks, w_vs, w_fc, w1, w2};
        __half*      d[8] = {predh, enth, wqh, wkh, wvh, wfh, w1h, w2h};
        int len4[8] = {MKV*DM/4, MQ*DM/4, DM*DM/4, DM*DM/4, DM*DM/4, DM*DM/4,
                       DI*DM/4, DM*DI/4};
        int acc = 0;
        for (int i = 0; i < 8; ++i) {
            a.src[i] = (const float4*)s[i];
            a.dst[i] = (uint2*)d[i];
            a.off[i] = acc;
            acc += len4[i];
        }
        a.off[8] = acc;
        cvt_all<<<(acc + 255) / 256, 256>>>(a);
    }

    // launches 1-3: Q, K, V projections (emit fp16 only)
    {
        dim3 grd(DM / PBN, (MQ + PBM - 1) / PBM);
        gemm_h<<<grd, 256, GEMM_SMEM>>>(enth, nullptr, wqh, b_qs,
                                        nullptr, qh, MQ, DM, DM, DM, 0, 0);
    }
    {
        dim3 grd(DM / PBN, (MKV + PBM - 1) / PBM);
        gemm_h<<<grd, 256, GEMM_SMEM>>>(predh, nullptr, wkh, b_ks,
                                        nullptr, kh, MKV, DM, DM, DM, 0, 0);
        gemm_h<<<grd, 256, GEMM_SMEM>>>(predh, nullptr, wvh, b_vs,
                                        nullptr, vh, MKV, DM, DM, DM, 0, 0);
    }
    // launch 4: tensor-core attention
    {
        dim3 grd((Lq + 63) / 64, NH, BSZ);
        attn_mma<<<grd, 128>>>(qh, kh, vh, amask, ctxh, Lq, Lv);
    }
    // launch 5: fc gemm (gathers valid rows); 6: ln1
    {
        dim3 grd(DM / PBN, (nv + PBM - 1) / PBM);
        gemm_h<<<grd, 256, GEMM_SMEM>>>(ctxh, gidx, wfh, b_fc,
                                        pT0, nullptr, nv, DM, DM, DM, 0, 0);
        ln_res<<<nv, 128>>>(pT0, nullptr, ent, gidx, ln1_g, ln1_b, pX, xh);
    }
    // launch 7: FFN1
    {
        dim3 grd(DI / PBN, (nv + PBM - 1) / PBM);
        gemm_h<<<grd, 256, GEMM_SMEM>>>(xh, nullptr, w1h, b1,
                                        nullptr, hh, nv, DI, DM, DM, 0, 1);
    }
    // launches 8-9: FFN2 split-K (K halves into t0/t1); 10: ln2
    {
        dim3 grd(DM / PBN, (nv + PBM - 1) / PBM);
        gemm_h<<<grd, 256, GEMM_SMEM>>>(hh, nullptr, w2h, b2,
                                        pT0, nullptr, nv, DM, DI/2, DI, 0, 0);
        gemm_h<<<grd, 256, GEMM_SMEM>>>(hh, nullptr, w2h, nullptr,
                                        pT1, nullptr, nv, DM, DI/2, DI, DI/2, 0);
        ln_res<<<nv, 128>>>(pT0, pT1, pX, nullptr, ln2_g, ln2_b, (float*)d_out, nullptr);
    }
}

// round 17
// speedup vs baseline: 5.7542x; 1.0198x over previous
#include <cuda_runtime.h>
#include <cuda_fp16.h>
#include <cstdint>
#include <math.h>

#define DM 512
#define DI 2048
#define NH 8
#define DKH 64
#define BSZ 32
#define MAXROWS (32*160)
#define MAXKV   (32*640)

// ---- fp32 scratch ----
__device__ float g_t0 [MAXROWS*DM];
__device__ float g_t1 [MAXROWS*DM];
__device__ float g_x  [MAXROWS*DM];
__device__ float g_bkv[2*DM];

// ---- fp16 scratch ----
__device__ __align__(16) __half g_predh[MAXKV*DM];
__device__ __align__(16) __half g_enth [MAXROWS*DM];
__device__ __align__(16) __half g_qh   [MAXROWS*DM];
__device__ __align__(16) __half g_kvh  [MAXKV*2*DM];   // [row][K(512) | V(512)]
__device__ __align__(16) __half g_ctxh [MAXROWS*DM];
__device__ __align__(16) __half g_xh   [MAXROWS*DM];
__device__ __align__(16) __half g_hh   [MAXROWS*DI];
__device__ __align__(16) __half g_wqh [DM*DM];
__device__ __align__(16) __half g_wkvh[2*DM*DM];       // rows 0-511 = wk, 512-1023 = wv
__device__ __align__(16) __half g_wfh [DM*DM];
__device__ __align__(16) __half g_w1h [DI*DM];
__device__ __align__(16) __half g_w2h [DM*DI];

__device__ __forceinline__ unsigned pack_h2(float a, float b) {
    __half2 t = __floats2half2_rn(a, b);
    return *(unsigned*)&t;
}

// ============================================================
// Fused fp32 -> fp16 conversion over 8 segments, ONE launch.
// ============================================================
struct CvtArgs {
    const float4* src[8];
    uint2*        dst[8];
    int           off[9];
};

__global__ void cvt_all(CvtArgs a)
{
    int i = blockIdx.x * blockDim.x + threadIdx.x;
    if (i >= a.off[8]) return;
    int s = 0;
    #pragma unroll
    for (int k = 1; k < 8; ++k) {
        if (i >= a.off[k]) s = k;
    }
    int local = i - a.off[s];
    float4 v = a.src[s][local];
    uint2 u;
    u.x = pack_h2(v.x, v.y);
    u.y = pack_h2(v.z, v.w);
    a.dst[s][local] = u;
}

__global__ void concat_bias(const float* __restrict__ b0, const float* __restrict__ b1,
                            float* __restrict__ out)
{
    int i = threadIdx.x + blockIdx.x * blockDim.x;   // 1024 threads
    out[i] = (i < DM) ? b0[i] : b1[i - DM];
}

// ============================================================
// shared helpers
// ============================================================
__device__ __forceinline__ unsigned smem_u32(const void* p) {
    return (unsigned)__cvta_generic_to_shared(p);
}
__device__ __forceinline__ void cp16(unsigned dst, const void* src, int sz) {
    asm volatile("cp.async.cg.shared.global [%0], [%1], 16, %2;"
        :: "r"(dst), "l"(src), "r"(sz) : "memory");
}
__device__ __forceinline__ void ldsm_x4(unsigned* r, const void* p) {
    unsigned a = smem_u32(p);
    asm volatile("ldmatrix.sync.aligned.m8n8.x4.shared.b16 {%0,%1,%2,%3}, [%4];"
        : "=r"(r[0]), "=r"(r[1]), "=r"(r[2]), "=r"(r[3]) : "r"(a));
}
__device__ __forceinline__ void ldsm_x2(unsigned* r, const void* p) {
    unsigned a = smem_u32(p);
    asm volatile("ldmatrix.sync.aligned.m8n8.x2.shared.b16 {%0,%1}, [%2];"
        : "=r"(r[0]), "=r"(r[1]) : "r"(a));
}
__device__ __forceinline__ void mma_h16(float* c, const unsigned* a, const unsigned* b) {
    asm volatile("mma.sync.aligned.m16n8k16.row.col.f32.f16.f16.f32 "
        "{%0,%1,%2,%3}, {%4,%5,%6,%7}, {%8,%9}, {%0,%1,%2,%3};"
        : "+f"(c[0]), "+f"(c[1]), "+f"(c[2]), "+f"(c[3])
        : "r"(a[0]), "r"(a[1]), "r"(a[2]), "r"(a[3]), "r"(b[0]), "r"(b[1]));
}

// ============================================================
// 2-stage pipelined fp16 mma.sync GEMM, BK=64, split-K capable.
// blockIdx.z==1: second K half, output -> Cf2, no bias.
// 128x128 tile, 256 thr, warp tile 64x32, rows padded to 144B.
// ============================================================
#define PBM 128
#define PBN 128
#define PBK 64
#define PLD 72
#define TILE_B (PBM*PLD*2)
#define STAGE_B (2*TILE_B)
#define GEMM_SMEM (2*STAGE_B)

__global__ __launch_bounds__(256, 2)
void gemm_h(const __half* __restrict__ A, const int* __restrict__ rmap,
            const __half* __restrict__ W, const float* __restrict__ bias,
            float* __restrict__ Cf, float* __restrict__ Cf2,
            __half* __restrict__ Ch,
            int M, int N, int Ksub, int lda, int k0, int relu)
{
    extern __shared__ char sm[];
    __shared__ int irows[PBM];

    if (blockIdx.z == 1) {
        Cf = Cf2;
        k0 += Ksub;
        bias = nullptr;
    }

    const int tid  = threadIdx.x;
    const int lane = tid & 31;
    const int wid  = tid >> 5;
    const int wm   = wid >> 2;
    const int wn   = wid & 3;
    const int bm = blockIdx.y * PBM;
    const int bn = blockIdx.x * PBN;

    if (tid < PBM) {
        int ar = bm + tid;
        irows[tid] = (ar < M) ? (rmap ? rmap[ar] : ar) : -1;
    }
    __syncthreads();

    const __half* srcs[2] = {A, W};

    float acc[4][4][4];
    #pragma unroll
    for (int mi = 0; mi < 4; ++mi) {
        #pragma unroll
        for (int ni = 0; ni < 4; ++ni) {
            #pragma unroll
            for (int j = 0; j < 4; ++j) acc[mi][ni][j] = 0.f;
        }
    }

    const unsigned smb = smem_u32(sm);
    const int nIter = Ksub / PBK;

    auto issue_stage = [&](int stage, int kblk) {
        #pragma unroll
        for (int i = 0; i < 8; ++i) {
            int idx = tid + i * 256;
            int buf = idx >> 10;
            int j   = idx & 1023;
            int r   = j >> 3;
            int c16 = j & 7;
            int grow;
            if (buf == 0) {
                grow = irows[r];
            } else {
                int wr = bn + r;
                grow = (wr < N) ? wr : -1;
            }
            unsigned dst = smb + stage * STAGE_B + buf * TILE_B + r * 144 + c16 * 16;
            const char* src = (const char*)srcs[buf]
                            + ((size_t)(grow < 0 ? 0 : grow) * lda + k0 + kblk) * 2 + c16 * 16;
            cp16(dst, src, grow >= 0 ? 16 : 0);
        }
        asm volatile("cp.async.commit_group;" ::: "memory");
    };

    issue_stage(0, 0);

    for (int c = 0; c < nIter; ++c) {
        if (c + 1 < nIter) {
            issue_stage((c + 1) & 1, (c + 1) * PBK);
            asm volatile("cp.async.wait_group 1;" ::: "memory");
        } else {
            asm volatile("cp.async.wait_group 0;" ::: "memory");
        }
        __syncthreads();

        char* st = sm + (c & 1) * STAGE_B;
        __half (*sA)[PLD] = (__half (*)[PLD])(st);
        __half (*sW)[PLD] = (__half (*)[PLD])(st + TILE_B);

        #pragma unroll
        for (int ks = 0; ks < 4; ++ks) {
            const int kk = ks * 16;
            unsigned av[4][4], bv[4][2];
            const int lr = lane & 15;
            const int lk = (lane >> 4) * 8;
            #pragma unroll
            for (int mi = 0; mi < 4; ++mi) {
                ldsm_x4(av[mi], &sA[wm * 64 + mi * 16 + lr][kk + lk]);
            }
            const int l8  = lane & 7;
            const int lk2 = ((lane >> 3) & 1) * 8;
            #pragma unroll
            for (int ni = 0; ni < 4; ++ni) {
                ldsm_x2(bv[ni], &sW[wn * 32 + ni * 8 + l8][kk + lk2]);
            }
            #pragma unroll
            for (int mi = 0; mi < 4; ++mi) {
                #pragma unroll
                for (int ni = 0; ni < 4; ++ni) {
                    mma_h16(acc[mi][ni], av[mi], bv[ni]);
                }
            }
        }
        __syncthreads();
    }

    #pragma unroll
    for (int mi = 0; mi < 4; ++mi) {
        int r0 = bm + wm * 64 + mi * 16 + (lane >> 2);
        #pragma unroll
        for (int ni = 0; ni < 4; ++ni) {
            int c = bn + wn * 32 + ni * 8 + (lane & 3) * 2;
            float b0 = bias ? bias[c]     : 0.f;
            float b1 = bias ? bias[c + 1] : 0.f;
            float v0 = acc[mi][ni][0] + b0;
            float v1 = acc[mi][ni][1] + b1;
            float v2 = acc[mi][ni][2] + b0;
            float v3 = acc[mi][ni][3] + b1;
            if (relu) {
                v0 = fmaxf(v0, 0.f); v1 = fmaxf(v1, 0.f);
                v2 = fmaxf(v2, 0.f); v3 = fmaxf(v3, 0.f);
            }
            if (r0 < M) {
                size_t o = (size_t)r0 * N + c;
                if (Cf) *(float2*)(Cf + o) = make_float2(v0, v1);
                if (Ch) *(unsigned*)(Ch + o) = pack_h2(v0, v1);
            }
            if (r0 + 8 < M) {
                size_t o = (size_t)(r0 + 8) * N + c;
                if (Cf) *(float2*)(Cf + o) = make_float2(v2, v3);
                if (Ch) *(unsigned*)(Ch + o) = pack_h2(v2, v3);
            }
        }
    }
}

// ============================================================
// LayerNorm with residual: out = LN(A (+A1) + R); optional fp16 out.
// ============================================================
__global__ void ln_res(const float* __restrict__ A, const float* __restrict__ A1,
                       const float* __restrict__ R, const int* __restrict__ rmap,
                       const float* __restrict__ g, const float* __restrict__ beta,
                       float* __restrict__ out, __half* __restrict__ outH)
{
    int row = blockIdx.x;
    int tid = threadIdx.x;   // 128
    __shared__ float red [128];
    __shared__ float red2[128];
    int rrow = rmap ? rmap[row] : row;
    float4 x = ((const float4*)(A + (size_t)row*DM))[tid];
    float4 r = ((const float4*)(R + (size_t)rrow*DM))[tid];
    x.x += r.x; x.y += r.y; x.z += r.z; x.w += r.w;
    if (A1) {
        float4 y = ((const float4*)(A1 + (size_t)row*DM))[tid];
        x.x += y.x; x.y += y.y; x.z += y.z; x.w += y.w;
    }
    red [tid] = x.x + x.y + x.z + x.w;
    red2[tid] = x.x*x.x + x.y*x.y + x.z*x.z + x.w*x.w;
    __syncthreads();
    #pragma unroll
    for (int o = 64; o > 0; o >>= 1) {
        if (tid < o) { red[tid] += red[tid+o]; red2[tid] += red2[tid+o]; }
        __syncthreads();
    }
    float mean = red[0] * (1.f/512.f);
    float var  = red2[0] * (1.f/512.f) - mean*mean;
    float inv  = rsqrtf(var + 1e-5f);
    float4 gg = ((const float4*)g)[tid];
    float4 bb = ((const float4*)beta)[tid];
    float4 o4;
    o4.x = (x.x - mean)*inv*gg.x + bb.x;
    o4.y = (x.y - mean)*inv*gg.y + bb.y;
    o4.z = (x.z - mean)*inv*gg.z + bb.z;
    o4.w = (x.w - mean)*inv*gg.w + bb.w;
    ((float4*)(out + (size_t)row*DM))[tid] = o4;
    if (outH) {
        size_t o = (size_t)row * DM + tid * 4;
        uint2 u;
        u.x = pack_h2(o4.x, o4.y);
        u.y = pack_h2(o4.z, o4.w);
        *(uint2*)(outH + o) = u;
    }
}

// ============================================================
// Tensor-core flash attention (passing). K/V from interleaved
// [row][1024] buffer: Kh = base, Vh = base + 512; stride kvs.
// ============================================================
#define NEG_BIAS (-30000.f)
#define KVS (2*DM)

__global__ __launch_bounds__(128, 2)
void attn_mma(const __half* __restrict__ Qh, const __half* __restrict__ KVh,
              const int* __restrict__ mask,
              __half* __restrict__ ctxH, int Lq, int Lv)
{
    __shared__ __half sQ [64][72];
    __shared__ __half sK [32][72];
    __shared__ __half sVt[64][40];
    __shared__ __half sB [64][36];
    __shared__ __half sP [4][16][40];

    const int qt = blockIdx.x, h = blockIdx.y, b = blockIdx.z;
    const int tid = threadIdx.x, lane = tid & 31, wid = tid >> 5;
    const int g = lane >> 2, tg = lane & 3;

    #pragma unroll
    for (int i = 0; i < 4; ++i) {
        int idx = tid + i * 128;
        int r = idx >> 3, c8 = idx & 7;
        int q = qt * 64 + r;
        uint4 v = make_uint4(0u, 0u, 0u, 0u);
        if (q < Lq) {
            v = *(const uint4*)(Qh + ((size_t)(b * Lq + q)) * DM + h * DKH + c8 * 8);
        }
        *(uint4*)&sQ[r][c8 * 8] = v;
    }
    __syncthreads();

    unsigned qf[4][4];
    {
        int lr = lane & 15, lk = (lane >> 4) * 8;
        #pragma unroll
        for (int kc = 0; kc < 4; ++kc) {
            ldsm_x4(qf[kc], &sQ[wid * 16 + lr][kc * 16 + lk]);
        }
    }

    float o[8][4];
    #pragma unroll
    for (int dt = 0; dt < 8; ++dt) {
        #pragma unroll
        for (int j = 0; j < 4; ++j) o[dt][j] = 0.f;
    }
    float mr0 = -1e30f, mr1 = -1e30f, lr0 = 0.f, lr1 = 0.f;

    for (int kv0 = 0; kv0 < Lv; kv0 += 32) {
        __syncthreads();

        #pragma unroll
        for (int i = 0; i < 2; ++i) {
            int idx = tid + i * 128;
            int r = idx >> 3, c8 = idx & 7;
            int kv = kv0 + r;
            uint4 kvv = make_uint4(0u, 0u, 0u, 0u);
            uint4 vvv = make_uint4(0u, 0u, 0u, 0u);
            if (kv < Lv) {
                size_t base = ((size_t)(b * Lv + kv)) * KVS + h * DKH + c8 * 8;
                kvv = *(const uint4*)(KVh + base);
                vvv = *(const uint4*)(KVh + base + DM);
            }
            *(uint4*)&sK[r][c8 * 8] = kvv;
            const __half* vh8 = (const __half*)&vvv;
            #pragma unroll
            for (int j = 0; j < 8; ++j) {
                sVt[c8 * 8 + j][r] = vh8[j];
            }
        }
        #pragma unroll
        for (int i = 0; i < 4; ++i) {
            int idx = tid + i * 128;
            int r = idx >> 3, c4 = (idx & 7) * 4;
            int q = qt * 64 + r;
            float f[4];
            if (q < Lq) {
                const int* mrow = mask + ((size_t)(b * Lq + q)) * Lv;
                #pragma unroll
                for (int j = 0; j < 4; ++j) {
                    int kv = kv0 + c4 + j;
                    int m = (kv < Lv) ? __ldg(mrow + kv) : 1;
                    f[j] = m ? NEG_BIAS : 0.f;
                }
            } else {
                f[0] = f[1] = f[2] = f[3] = NEG_BIAS;
            }
            uint2 u;
            u.x = pack_h2(f[0], f[1]);
            u.y = pack_h2(f[2], f[3]);
            *(uint2*)&sB[r][c4] = u;
        }
        __syncthreads();

        float sc[4][4];
        #pragma unroll
        for (int nt = 0; nt < 4; ++nt) {
            #pragma unroll
            for (int j = 0; j < 4; ++j) sc[nt][j] = 0.f;
        }
        {
            int l8 = lane & 7, lk2 = ((lane >> 3) & 1) * 8;
            #pragma unroll
            for (int nt = 0; nt < 4; ++nt) {
                #pragma unroll
                for (int kc = 0; kc < 4; ++kc) {
                    unsigned bf[2];
                    ldsm_x2(bf, &sK[nt * 8 + l8][kc * 16 + lk2]);
                    mma_h16(sc[nt], qf[kc], bf);
                }
            }
        }

        float tm0 = -1e30f, tm1 = -1e30f;
        #pragma unroll
        for (int nt = 0; nt < 4; ++nt) {
            __half2 hb0 = *(__half2*)&sB[wid * 16 + g][nt * 8 + tg * 2];
            __half2 hb1 = *(__half2*)&sB[wid * 16 + g + 8][nt * 8 + tg * 2];
            float2 b0 = __half22float2(hb0);
            float2 b1 = __half22float2(hb1);
            sc[nt][0] = sc[nt][0] * 0.125f + b0.x;
            sc[nt][1] = sc[nt][1] * 0.125f + b0.y;
            sc[nt][2] = sc[nt][2] * 0.125f + b1.x;
            sc[nt][3] = sc[nt][3] * 0.125f + b1.y;
            tm0 = fmaxf(tm0, fmaxf(sc[nt][0], sc[nt][1]));
            tm1 = fmaxf(tm1, fmaxf(sc[nt][2], sc[nt][3]));
        }
        tm0 = fmaxf(tm0, __shfl_xor_sync(0xffffffffu, tm0, 1));
        tm0 = fmaxf(tm0, __shfl_xor_sync(0xffffffffu, tm0, 2));
        tm1 = fmaxf(tm1, __shfl_xor_sync(0xffffffffu, tm1, 1));
        tm1 = fmaxf(tm1, __shfl_xor_sync(0xffffffffu, tm1, 2));

        float mn0 = fmaxf(mr0, tm0);
        float mn1 = fmaxf(mr1, tm1);
        float s0 = __expf(mr0 - mn0);
        float s1 = __expf(mr1 - mn1);

        float ts0 = 0.f, ts1 = 0.f;
        #pragma unroll
        for (int nt = 0; nt < 4; ++nt) {
            sc[nt][0] = __expf(sc[nt][0] - mn0);
            sc[nt][1] = __expf(sc[nt][1] - mn0);
            sc[nt][2] = __expf(sc[nt][2] - mn1);
            sc[nt][3] = __expf(sc[nt][3] - mn1);
            ts0 += sc[nt][0] + sc[nt][1];
            ts1 += sc[nt][2] + sc[nt][3];
        }
        ts0 += __shfl_xor_sync(0xffffffffu, ts0, 1);
        ts0 += __shfl_xor_sync(0xffffffffu, ts0, 2);
        ts1 += __shfl_xor_sync(0xffffffffu, ts1, 1);
        ts1 += __shfl_xor_sync(0xffffffffu, ts1, 2);

        lr0 = lr0 * s0 + ts0;
        lr1 = lr1 * s1 + ts1;
        mr0 = mn0;
        mr1 = mn1;
        #pragma unroll
        for (int dt = 0; dt < 8; ++dt) {
            o[dt][0] *= s0; o[dt][1] *= s0;
            o[dt][2] *= s1; o[dt][3] *= s1;
        }

        #pragma unroll
        for (int nt = 0; nt < 4; ++nt) {
            *(unsigned*)&sP[wid][g][nt * 8 + tg * 2]     = pack_h2(sc[nt][0], sc[nt][1]);
            *(unsigned*)&sP[wid][g + 8][nt * 8 + tg * 2] = pack_h2(sc[nt][2], sc[nt][3]);
        }
        __syncwarp();

        {
            int lr = lane & 15, lk = (lane >> 4) * 8;
            int l8 = lane & 7, lk2 = ((lane >> 3) & 1) * 8;
            #pragma unroll
            for (int kc2 = 0; kc2 < 2; ++kc2) {
                unsigned pA[4];
                ldsm_x4(pA, &sP[wid][lr][kc2 * 16 + lk]);
                #pragma unroll
                for (int ni = 0; ni < 8; ++ni) {
                    unsigned bf[2];
                    ldsm_x2(bf, &sVt[ni * 8 + l8][kc2 * 16 + lk2]);
                    mma_h16(o[ni], pA, bf);
                }
            }
        }
        __syncwarp();
    }

    float inv0 = 1.f / lr0;
    float inv1 = 1.f / lr1;
    int q0 = qt * 64 + wid * 16 + g;
    int q1 = q0 + 8;
    #pragma unroll
    for (int dt = 0; dt < 8; ++dt) {
        int col = h * DKH + dt * 8 + tg * 2;
        if (q0 < Lq) {
            *(unsigned*)(ctxH + ((size_t)(b * Lq + q0)) * DM + col)
                = pack_h2(o[dt][0] * inv0, o[dt][1] * inv0);
        }
        if (q1 < Lq) {
            *(unsigned*)(ctxH + ((size_t)(b * Lq + q1)) * DM + col)
                = pack_h2(o[dt][2] * inv1, o[dt][3] * inv1);
        }
    }
}

// ============================================================
// launcher
// ============================================================
extern "C" void kernel_launch(void* const* d_in, const int* in_sizes, int n_in,
                              void* d_out, int out_size)
{
    const float* ent   = (const float*)d_in[0];
    const float* pred  = (const float*)d_in[1];
    const float* w_qs  = (const float*)d_in[2];
    const float* b_qs  = (const float*)d_in[3];
    const float* w_ks  = (const float*)d_in[4];
    const float* b_ks  = (const float*)d_in[5];
    const float* w_vs  = (const float*)d_in[6];
    const float* b_vs  = (const float*)d_in[7];
    const float* w_fc  = (const float*)d_in[8];
    const float* b_fc  = (const float*)d_in[9];
    const float* ln1_g = (const float*)d_in[10];
    const float* ln1_b = (const float*)d_in[11];
    const float* w1    = (const float*)d_in[12];
    const float* b1    = (const float*)d_in[13];
    const float* w2    = (const float*)d_in[14];
    const float* b2    = (const float*)d_in[15];
    const float* ln2_g = (const float*)d_in[16];
    const float* ln2_b = (const float*)d_in[17];
    const int*   amask = (const int*)d_in[18];
    const int*   gidx  = (const int*)d_in[20];

    int Lq  = in_sizes[0] / (BSZ * DM);
    int Lv  = in_sizes[1] / (BSZ * DM);
    int nv  = in_sizes[20];
    int MKV = BSZ * Lv;
    int MQ  = BSZ * Lq;

    float *pT0, *pT1, *pX, *pBkv;
    cudaGetSymbolAddress((void**)&pT0,  g_t0);
    cudaGetSymbolAddress((void**)&pT1,  g_t1);
    cudaGetSymbolAddress((void**)&pX,   g_x);
    cudaGetSymbolAddress((void**)&pBkv, g_bkv);

    __half *predh, *enth, *qh, *kvh, *ctxh, *xh, *hh;
    __half *wqh, *wkvh, *wfh, *w1h, *w2h;
    cudaGetSymbolAddress((void**)&predh, g_predh);
    cudaGetSymbolAddress((void**)&enth,  g_enth);
    cudaGetSymbolAddress((void**)&qh,    g_qh);
    cudaGetSymbolAddress((void**)&kvh,   g_kvh);
    cudaGetSymbolAddress((void**)&ctxh,  g_ctxh);
    cudaGetSymbolAddress((void**)&xh,    g_xh);
    cudaGetSymbolAddress((void**)&hh,    g_hh);
    cudaGetSymbolAddress((void**)&wqh,   g_wqh);
    cudaGetSymbolAddress((void**)&wkvh,  g_wkvh);
    cudaGetSymbolAddress((void**)&wfh,   g_wfh);
    cudaGetSymbolAddress((void**)&w1h,   g_w1h);
    cudaGetSymbolAddress((void**)&w2h,   g_w2h);

    cudaFuncSetAttribute(gemm_h, cudaFuncAttributeMaxDynamicSharedMemorySize, GEMM_SMEM);

    // ---- launch 0: all conversions fused (wk/wv -> concatenated wkv) ----
    {
        CvtArgs a;
        const float* s[8] = {pred, ent, w_qs, w_ks, w_vs, w_fc, w1, w2};
        __half*      d[8] = {predh, enth, wqh, wkvh, wkvh + (size_t)DM * DM,
                             wfh, w1h, w2h};
        int len4[8] = {MKV*DM/4, MQ*DM/4, DM*DM/4, DM*DM/4, DM*DM/4, DM*DM/4,
                       DI*DM/4, DM*DI/4};
        int acc = 0;
        for (int i = 0; i < 8; ++i) {
            a.src[i] = (const float4*)s[i];
            a.dst[i] = (uint2*)d[i];
            a.off[i] = acc;
            acc += len4[i];
        }
        a.off[8] = acc;
        cvt_all<<<(acc + 255) / 256, 256>>>(a);
    }
    // launch 1: bias concat for fused KV gemm
    concat_bias<<<1, 2 * DM>>>(b_ks, b_vs, pBkv);

    // launch 2: Q projection
    {
        dim3 grd(DM / PBN, (MQ + PBM - 1) / PBM);
        gemm_h<<<grd, 256, GEMM_SMEM>>>(enth, nullptr, wqh, b_qs,
                                        nullptr, nullptr, qh, MQ, DM, DM, DM, 0, 0);
    }
    // launch 3: fused K+V projection (N=1024)
    {
        dim3 grd(2 * DM / PBN, (MKV + PBM - 1) / PBM);
        gemm_h<<<grd, 256, GEMM_SMEM>>>(predh, nullptr, wkvh, pBkv,
                                        nullptr, nullptr, kvh, MKV, 2 * DM, DM, DM, 0, 0);
    }
    // launch 4: tensor-core attention
    {
        dim3 grd((Lq + 63) / 64, NH, BSZ);
        attn_mma<<<grd, 128>>>(qh, kvh, amask, ctxh, Lq, Lv);
    }
    // launch 5: fc gemm (gathers valid rows); 6: ln1
    {
        dim3 grd(DM / PBN, (nv + PBM - 1) / PBM);
        gemm_h<<<grd, 256, GEMM_SMEM>>>(ctxh, gidx, wfh, b_fc,
                                        pT0, nullptr, nullptr, nv, DM, DM, DM, 0, 0);
        ln_res<<<nv, 128>>>(pT0, nullptr, ent, gidx, ln1_g, ln1_b, pX, xh);
    }
    // launch 7: FFN1
    {
        dim3 grd(DI / PBN, (nv + PBM - 1) / PBM);
        gemm_h<<<grd, 256, GEMM_SMEM>>>(xh, nullptr, w1h, b1,
                                        nullptr, nullptr, hh, nv, DI, DM, DM, 0, 1);
    }
    // launch 8: FFN2 split-K via gridDim.z=2; 9: ln2
    {
        dim3 grd(DM / PBN, (nv + PBM - 1) / PBM, 2);
        gemm_h<<<grd, 256, GEMM_SMEM>>>(hh, nullptr, w2h, b2,
                                        pT0, pT1, nullptr, nv, DM, DI/2, DI, 0, 0);
        ln_res<<<nv, 128>>>(pT0, pT1, pX, nullptr, ln2_g, ln2_b, (float*)d_out, nullptr);
    }
}